// round 8
// baseline (speedup 1.0000x reference)
#include <cuda_runtime.h>
#include <cuda_fp16.h>
#include <math.h>
#include <stdint.h>

// ---------------------------------------------------------------------------
// Problem constants
// ---------------------------------------------------------------------------
#define B_  16
#define C_  512
#define N_  1024
#define HW  32
#define SPITCH 12                      // smem row stride in u32 (48B) - conflict-free
#define NSTG 4                         // pipeline stages
#define STGSZ (128 * SPITCH * 4)       // 6144 B per matrix per stage
#define SMEM_DYN (2 * NSTG * STGSZ)    // 49152 B

static constexpr size_t TSZ  = (size_t)B_ * C_ * N_;
static constexpr size_t SSZ  = (size_t)B_ * N_ * N_;
static constexpr size_t WTSZ = (size_t)9 * C_ * (2 * C_);

// ---------------------------------------------------------------------------
// Scratch (static device globals; no allocation anywhere)
// ---------------------------------------------------------------------------
__device__ float g_S1[SSZ], g_S2[SSZ], g_S3[SSZ], g_St[SSZ];
__device__ float g_O1[TSZ], g_O2[TSZ], g_a[TSZ];
__device__ float g_ex[TSZ], g_q [TSZ], g_q1[TSZ];
__device__ float g_r [TSZ], g_u [TSZ], g_c [TSZ];

__device__ __align__(128) __half g_P16  [SSZ];                     // probs [n][m]
__device__ __align__(128) __half g_ex16 [TSZ], g_q16 [TSZ], g_q116[TSZ];  // [c][n]
__device__ __align__(128) __half g_exT16[TSZ], g_qT16[TSZ], g_q1T16[TSZ]; // [n][c]
__device__ __align__(128) __half g_O1T16[TSZ], g_O2T16[TSZ];       // [p][c]
__device__ __align__(128) __half g_aT16 [TSZ], g_rhT16[TSZ];       // [p][c]
__device__ __align__(128) __half g_in1T16[TSZ], g_in2T16[TSZ], g_in3T16[TSZ];
__device__ __align__(128) __half g_wf16[WTSZ], g_wo16[WTSZ];       // [tap][co][ci]
__device__ __align__(128) __half g_wru16[(size_t)(2 * C_) * (2 * C_)];
__device__ __align__(128) __half g_wc16 [(size_t)C_ * (2 * C_)];

// ---------------------------------------------------------------------------
// cp.async helpers
// ---------------------------------------------------------------------------
__device__ __forceinline__ void cpa16(uint32_t dst, const void* src, uint32_t sz) {
    asm volatile("cp.async.ca.shared.global [%0], [%1], 16, %2;"
                 :: "r"(dst), "l"(src), "r"(sz) : "memory");
}
#define CP_COMMIT() asm volatile("cp.async.commit_group;" ::: "memory")
#define CP_WAIT2()  asm volatile("cp.async.wait_group 2;" ::: "memory")

// ---------------------------------------------------------------------------
// fp16 mma.sync microkernel: 8 warps, warp tile 32x64, block tile 128x128
// smem: half2-packed operands [row][kpair], stride SPITCH u32, ldmatrix loads.
// ---------------------------------------------------------------------------
__device__ __forceinline__ void mma16(float* d, const uint32_t* a, uint32_t b0, uint32_t b1) {
    asm volatile(
        "mma.sync.aligned.m16n8k16.row.col.f32.f16.f16.f32 "
        "{%0,%1,%2,%3}, {%4,%5,%6,%7}, {%8,%9}, {%0,%1,%2,%3};\n"
        : "+f"(d[0]), "+f"(d[1]), "+f"(d[2]), "+f"(d[3])
        : "r"(a[0]), "r"(a[1]), "r"(a[2]), "r"(a[3]), "r"(b0), "r"(b1));
}

__device__ __forceinline__ void ldsm4(uint32_t* r, uint32_t addr) {
    asm volatile(
        "ldmatrix.sync.aligned.m8n8.x4.shared.b16 {%0,%1,%2,%3}, [%4];"
        : "=r"(r[0]), "=r"(r[1]), "=r"(r[2]), "=r"(r[3]) : "r"(addr));
}

// One K=16 slab, warp tile 32x64: 2 m-tiles x 8 n-tiles of m16n8k16
__device__ __forceinline__ void compute16(uint32_t aB, uint32_t bB,
                                          float (*acc)[8][4], int wm, int wn,
                                          int lane) {
    int lr = lane & 15;
    uint32_t lc = (uint32_t)(lane >> 4) * 16;
    uint32_t a[2][4], b[4][4];
#pragma unroll
    for (int mt = 0; mt < 2; ++mt)
        ldsm4(a[mt], aB + (uint32_t)(wm + mt * 16 + lr) * (SPITCH * 4) + lc);
#pragma unroll
    for (int np = 0; np < 4; ++np)
        ldsm4(b[np], bB + (uint32_t)(wn + np * 16 + lr) * (SPITCH * 4) + lc);
#pragma unroll
    for (int mt = 0; mt < 2; ++mt)
#pragma unroll
        for (int np = 0; np < 4; ++np) {
            mma16(acc[mt][2 * np],     a[mt], b[np][0], b[np][2]);
            mma16(acc[mt][2 * np + 1], a[mt], b[np][1], b[np][3]);
        }
}

#define ZERO_ACC(acc)                                       \
    float acc[2][8][4];                                     \
    _Pragma("unroll")                                       \
    for (int i_ = 0; i_ < 2; ++i_)                          \
        _Pragma("unroll")                                   \
        for (int j_ = 0; j_ < 8; ++j_)                      \
            _Pragma("unroll")                               \
            for (int v_ = 0; v_ < 4; ++v_) acc[i_][j_][v_] = 0.f;

// 256 threads: warp grid 4(m) x 2(n); staging threads 0-127 -> A, 128-255 -> B
#define GEMM_PRE()                                                           \
    extern __shared__ __align__(1024) char dsm[];                            \
    int t = threadIdx.x, lane = t & 31, wid = t >> 5;                        \
    int wm = (wid & 3) * 32, wn = (wid >> 2) * 64;                           \
    int g = lane >> 2, tg = lane & 3;                                        \
    int lr_ = t & 127; bool isA_ = t < 128;                                  \
    uint32_t sAs = (uint32_t)__cvta_generic_to_shared(dsm);                  \
    uint32_t sBs = sAs + NSTG * STGSZ;                                       \
    uint32_t stgb = (isA_ ? sAs : sBs) + (uint32_t)lr_ * 48;                 \
    (void)g; (void)tg;

#define GEMM_PIPE(KI, ISSUE, acc)                                            \
    for (int s_ = 0; s_ < 3; ++s_) { ISSUE(s_); CP_COMMIT(); }               \
    for (int it_ = 0; it_ < (KI); ++it_) {                                   \
        CP_WAIT2();                                                          \
        __syncthreads();                                                     \
        compute16(sAs + (it_ & 3) * STGSZ, sBs + (it_ & 3) * STGSZ,          \
                  acc, wm, wn, lane);                                        \
        if (it_ + 3 < (KI)) ISSUE(it_ + 3);                                  \
        CP_COMMIT();                                                         \
    }

// ---------------------------------------------------------------------------
// k_scores: S[b,n,m] = sum_c ET[n,c] * QT[m,c].  grid (8,8,16), 256 thr
// ---------------------------------------------------------------------------
__global__ void __launch_bounds__(256, 2) k_scores(const __half* __restrict__ ET,
                                                   const __half* __restrict__ QT,
                                                   float* __restrict__ S) {
    GEMM_PRE();
    int b = blockIdx.z;
    int n0 = blockIdx.y * 128, m0 = blockIdx.x * 128;
    const __half* myrow = isA_
        ? (ET + (size_t)b * N_ * C_ + (size_t)(n0 + lr_) * C_)
        : (QT + (size_t)b * N_ * C_ + (size_t)(m0 + lr_) * C_);
    float* Sb = S + (size_t)b * N_ * N_;

    auto issue = [&](int it) {
        uint32_t d = stgb + (it & 3) * STGSZ;
        const __half* p = myrow + it * 16;
        cpa16(d, p, 16); cpa16(d + 16, p + 8, 16);
    };

    ZERO_ACC(acc);
    GEMM_PIPE(C_ / 16, issue, acc);

#pragma unroll
    for (int mt = 0; mt < 2; ++mt)
#pragma unroll
        for (int nt = 0; nt < 8; ++nt) {
            int row = n0 + wm + mt * 16 + g;
            int col = m0 + wn + nt * 8 + tg * 2;
            *(float2*)(Sb + (size_t)row * N_ + col)       = make_float2(acc[mt][nt][0], acc[mt][nt][1]);
            *(float2*)(Sb + (size_t)(row + 8) * N_ + col) = make_float2(acc[mt][nt][2], acc[mt][nt][3]);
        }
}

// ---------------------------------------------------------------------------
// Row softmax: read fp32 scores, write fp16 probs. grid B_*N_, 256 thr
// ---------------------------------------------------------------------------
__global__ void __launch_bounds__(256) k_softmaxP(const float* __restrict__ S,
                                                  __half* __restrict__ P) {
    const float* row = S + (size_t)blockIdx.x * N_;
    __half*      out = P + (size_t)blockIdx.x * N_;
    int t = threadIdx.x;
    float4 v = *(const float4*)(row + 4 * t);
    __shared__ float red[8];

    float m = fmaxf(fmaxf(v.x, v.y), fmaxf(v.z, v.w));
#pragma unroll
    for (int o = 16; o; o >>= 1) m = fmaxf(m, __shfl_xor_sync(0xffffffffu, m, o));
    if ((t & 31) == 0) red[t >> 5] = m;
    __syncthreads();
    float mx = red[0];
#pragma unroll
    for (int i = 1; i < 8; ++i) mx = fmaxf(mx, red[i]);
    __syncthreads();

    v.x = __expf(v.x - mx); v.y = __expf(v.y - mx);
    v.z = __expf(v.z - mx); v.w = __expf(v.w - mx);
    float s = v.x + v.y + v.z + v.w;
#pragma unroll
    for (int o = 16; o; o >>= 1) s += __shfl_xor_sync(0xffffffffu, s, o);
    if ((t & 31) == 0) red[t >> 5] = s;
    __syncthreads();
    float tot = red[0];
#pragma unroll
    for (int i = 1; i < 8; ++i) tot += red[i];
    float inv = 1.f / tot;

    *(__half2*)(out + 4 * t)     = __floats2half2_rn(v.x * inv, v.y * inv);
    *(__half2*)(out + 4 * t + 2) = __floats2half2_rn(v.z * inv, v.w * inv);
}

// ---------------------------------------------------------------------------
// k_attmm: O[b,c,n] = sum_m Q16[c,m] * P[n,m].  grid (8,4,16), 256 thr
// ---------------------------------------------------------------------------
__global__ void __launch_bounds__(256, 2) k_attmm(const __half* __restrict__ Q16,
                                                  const __half* __restrict__ P,
                                                  float* __restrict__ O) {
    GEMM_PRE();
    int b = blockIdx.z;
    int c0 = blockIdx.y * 128, n0 = blockIdx.x * 128;
    const __half* myrow = isA_
        ? (Q16 + (size_t)b * C_ * N_ + (size_t)(c0 + lr_) * N_)
        : (P   + (size_t)b * N_ * N_ + (size_t)(n0 + lr_) * N_);
    float* Ob = O + (size_t)b * C_ * N_;

    auto issue = [&](int it) {
        uint32_t d = stgb + (it & 3) * STGSZ;
        const __half* p = myrow + it * 16;
        cpa16(d, p, 16); cpa16(d + 16, p + 8, 16);
    };

    ZERO_ACC(acc);
    GEMM_PIPE(N_ / 16, issue, acc);

#pragma unroll
    for (int mt = 0; mt < 2; ++mt)
#pragma unroll
        for (int nt = 0; nt < 8; ++nt) {
            int row = c0 + wm + mt * 16 + g;
            int col = n0 + wn + nt * 8 + tg * 2;
            *(float2*)(Ob + (size_t)row * N_ + col)       = make_float2(acc[mt][nt][0], acc[mt][nt][1]);
            *(float2*)(Ob + (size_t)(row + 8) * N_ + col) = make_float2(acc[mt][nt][2], acc[mt][nt][3]);
        }
}

// ---------------------------------------------------------------------------
// k_gemmRU: fused reset+update GEMM, M=1024, B=[xT;hT]. grid (8,8,16), 256 thr
// ---------------------------------------------------------------------------
__global__ void __launch_bounds__(256, 2) k_gemmRU(const __half* __restrict__ Wru,
                                                   const __half* __restrict__ xT,
                                                   const __half* __restrict__ hT,
                                                   const float* __restrict__ b_r,
                                                   const float* __restrict__ b_u,
                                                   float* __restrict__ R,
                                                   float* __restrict__ U) {
    GEMM_PRE();
    int b = blockIdx.z;
    int co0 = blockIdx.y * 128, p0 = blockIdx.x * 128;
    const __half* arow = Wru + (size_t)(co0 + lr_) * (2 * C_);
    const __half* xrow = xT + (size_t)b * N_ * C_ + (size_t)(p0 + lr_) * C_;
    const __half* hrow = hT + (size_t)b * N_ * C_ + (size_t)(p0 + lr_) * C_;

    auto issue = [&](int it) {
        uint32_t d = stgb + (it & 3) * STGSZ;
        int ci0 = it * 16;
        const __half* p = isA_ ? (arow + ci0)
                               : ((ci0 < C_) ? (xrow + ci0) : (hrow + ci0 - C_));
        cpa16(d, p, 16); cpa16(d + 16, p + 8, 16);
    };

    ZERO_ACC(acc);
    GEMM_PIPE((2 * C_) / 16, issue, acc);

    bool isR = co0 < C_;
    float* dst = (isR ? R : U) + (size_t)b * C_ * N_;
    int rbase = isR ? co0 : (co0 - C_);
    const float* bias = isR ? b_r : b_u;
#pragma unroll
    for (int mt = 0; mt < 2; ++mt)
#pragma unroll
        for (int nt = 0; nt < 8; ++nt) {
            int row = rbase + wm + mt * 16 + g;
            int col = p0 + wn + nt * 8 + tg * 2;
            float bv0 = bias[row], bv1 = bias[row + 8];
            float o0 = 1.f / (1.f + __expf(-(acc[mt][nt][0] + bv0)));
            float o1 = 1.f / (1.f + __expf(-(acc[mt][nt][1] + bv0)));
            float o2 = 1.f / (1.f + __expf(-(acc[mt][nt][2] + bv1)));
            float o3 = 1.f / (1.f + __expf(-(acc[mt][nt][3] + bv1)));
            *(float2*)(dst + (size_t)row * N_ + col)       = make_float2(o0, o1);
            *(float2*)(dst + (size_t)(row + 8) * N_ + col) = make_float2(o2, o3);
        }
}

// ---------------------------------------------------------------------------
// k_gemmCAND: c = tanh(Wc @ [x ; r*h] + b).  grid (8,4,16), 256 thr
// ---------------------------------------------------------------------------
__global__ void __launch_bounds__(256, 2) k_gemmCAND(const __half* __restrict__ Wc,
                                                     const __half* __restrict__ xT,
                                                     const __half* __restrict__ rhT,
                                                     const float* __restrict__ bias,
                                                     float* __restrict__ Y) {
    GEMM_PRE();
    int b = blockIdx.z;
    int co0 = blockIdx.y * 128, p0 = blockIdx.x * 128;
    const __half* arow  = Wc + (size_t)(co0 + lr_) * (2 * C_);
    const __half* xrow  = xT  + (size_t)b * N_ * C_ + (size_t)(p0 + lr_) * C_;
    const __half* rhrow = rhT + (size_t)b * N_ * C_ + (size_t)(p0 + lr_) * C_;
    float* Yb = Y + (size_t)b * C_ * N_;

    auto issue = [&](int it) {
        uint32_t d = stgb + (it & 3) * STGSZ;
        int ci0 = it * 16;
        const __half* p = isA_ ? (arow + ci0)
                               : ((ci0 < C_) ? (xrow + ci0) : (rhrow + ci0 - C_));
        cpa16(d, p, 16); cpa16(d + 16, p + 8, 16);
    };

    ZERO_ACC(acc);
    GEMM_PIPE((2 * C_) / 16, issue, acc);

#pragma unroll
    for (int mt = 0; mt < 2; ++mt)
#pragma unroll
        for (int nt = 0; nt < 8; ++nt) {
            int row = co0 + wm + mt * 16 + g;
            int col = p0 + wn + nt * 8 + tg * 2;
            float bv0 = bias[row], bv1 = bias[row + 8];
            *(float2*)(Yb + (size_t)row * N_ + col) =
                make_float2(tanhf(acc[mt][nt][0] + bv0), tanhf(acc[mt][nt][1] + bv0));
            *(float2*)(Yb + (size_t)(row + 8) * N_ + col) =
                make_float2(tanhf(acc[mt][nt][2] + bv1), tanhf(acc[mt][nt][3] + bv1));
        }
}

// ---------------------------------------------------------------------------
// k_conv3: 3x3 conv pad 1, implicit GEMM K=9216. grid (8,4,16), 256 thr
// ---------------------------------------------------------------------------
__global__ void __launch_bounds__(256, 2) k_conv3(const __half* __restrict__ Wt,
                                                  const __half* __restrict__ x0T,
                                                  const __half* __restrict__ x1T,
                                                  const float* __restrict__ bias,
                                                  float* __restrict__ Y) {
    GEMM_PRE();
    int b = blockIdx.z;
    int co0 = blockIdx.y * 128, p0 = blockIdx.x * 128;
    const __half* x0b = x0T + (size_t)b * N_ * C_;
    const __half* x1b = x1T + (size_t)b * N_ * C_;
    float* Yb = Y + (size_t)b * C_ * N_;

    int p = p0 + lr_;
    int py = p >> 5, px = p & 31;

    auto issue = [&](int it) {
        int tap = it >> 6, ci0 = (it & 63) * 16;
        uint32_t d = stgb + (it & 3) * STGSZ;
        if (isA_) {
            const __half* pa = Wt + ((size_t)tap * C_ + co0 + lr_) * (2 * C_) + ci0;
            cpa16(d, pa, 16); cpa16(d + 16, pa + 8, 16);
        } else {
            int dy = tap / 3 - 1, dx = tap % 3 - 1;
            int y = py + dy, x = px + dx;
            bool ok = ((unsigned)y < HW) && ((unsigned)x < HW);
            int pp = ok ? (y * HW + x) : 0;
            const __half* pb = (ci0 < C_) ? (x0b + (size_t)pp * C_ + ci0)
                                          : (x1b + (size_t)pp * C_ + ci0 - C_);
            uint32_t sz = ok ? 16u : 0u;
            cpa16(d, pb, sz); cpa16(d + 16, pb + 8, sz);
        }
    };

    ZERO_ACC(acc);
    GEMM_PIPE(9 * (2 * C_) / 16, issue, acc);

#pragma unroll
    for (int mt = 0; mt < 2; ++mt)
#pragma unroll
        for (int nt = 0; nt < 8; ++nt) {
            int row = co0 + wm + mt * 16 + g;
            int col = p0 + wn + nt * 8 + tg * 2;
            float bv0 = bias[row], bv1 = bias[row + 8];
            *(float2*)(Yb + (size_t)row * N_ + col)       = make_float2(acc[mt][nt][0] + bv0, acc[mt][nt][1] + bv0);
            *(float2*)(Yb + (size_t)(row + 8) * N_ + col) = make_float2(acc[mt][nt][2] + bv1, acc[mt][nt][3] + bv1);
        }
}

// ---------------------------------------------------------------------------
// fp32 NxN per-batch transpose (for score reuse). grid (32,32,B_), block (32,8)
// ---------------------------------------------------------------------------
__global__ void k_trS(const float* __restrict__ in, float* __restrict__ out) {
    __shared__ float tile[32][33];
    int b = blockIdx.z;
    const float* ib = in + (size_t)b * N_ * N_;
    float*       ob = out + (size_t)b * N_ * N_;
    int x0 = blockIdx.x * 32, y0 = blockIdx.y * 32;
    int tx = threadIdx.x, ty = threadIdx.y;
#pragma unroll
    for (int j = 0; j < 4; ++j)
        tile[ty + 8 * j][tx] = ib[(size_t)(y0 + ty + 8 * j) * N_ + x0 + tx];
    __syncthreads();
#pragma unroll
    for (int j = 0; j < 4; ++j)
        ob[(size_t)(x0 + ty + 8 * j) * N_ + y0 + tx] = tile[tx][ty + 8 * j];
}

// ---------------------------------------------------------------------------
// Transpose/convert kernels. grid (N_/32, C_/32, B_), block (32,8)
// ---------------------------------------------------------------------------
__global__ void k_tr2(const float* __restrict__ in, __half* __restrict__ outN,
                      __half* __restrict__ outT) {
    __shared__ float tile[32][33];
    int b = blockIdx.z;
    const float* ib = in + (size_t)b * C_ * N_;
    __half* on = outN + (size_t)b * C_ * N_;
    __half* ot = outT + (size_t)b * N_ * C_;
    int n0 = blockIdx.x * 32, c0 = blockIdx.y * 32;
    int tx = threadIdx.x, ty = threadIdx.y;
#pragma unroll
    for (int j = 0; j < 4; ++j) {
        float v = ib[(size_t)(c0 + ty + 8 * j) * N_ + n0 + tx];
        tile[ty + 8 * j][tx] = v;
        on[(size_t)(c0 + ty + 8 * j) * N_ + n0 + tx] = __float2half_rn(v);
    }
    __syncthreads();
#pragma unroll
    for (int j = 0; j < 4; ++j)
        ot[(size_t)(n0 + ty + 8 * j) * C_ + c0 + tx] = __float2half_rn(tile[tx][ty + 8 * j]);
}

__global__ void k_trh(const float* __restrict__ in, __half* __restrict__ outT) {
    __shared__ float tile[32][33];
    int b = blockIdx.z;
    const float* ib = in + (size_t)b * C_ * N_;
    __half* ot = outT + (size_t)b * N_ * C_;
    int n0 = blockIdx.x * 32, c0 = blockIdx.y * 32;
    int tx = threadIdx.x, ty = threadIdx.y;
#pragma unroll
    for (int j = 0; j < 4; ++j)
        tile[ty + 8 * j][tx] = ib[(size_t)(c0 + ty + 8 * j) * N_ + n0 + tx];
    __syncthreads();
#pragma unroll
    for (int j = 0; j < 4; ++j)
        ot[(size_t)(n0 + ty + 8 * j) * C_ + c0 + tx] = __float2half_rn(tile[tx][ty + 8 * j]);
}

__global__ void k_rh(const float* __restrict__ r, const float* __restrict__ h,
                     __half* __restrict__ outT) {
    __shared__ float tile[32][33];
    int b = blockIdx.z;
    const float* rb = r + (size_t)b * C_ * N_;
    const float* hb = h + (size_t)b * C_ * N_;
    __half* ot = outT + (size_t)b * N_ * C_;
    int n0 = blockIdx.x * 32, c0 = blockIdx.y * 32;
    int tx = threadIdx.x, ty = threadIdx.y;
#pragma unroll
    for (int j = 0; j < 4; ++j) {
        size_t idx = (size_t)(c0 + ty + 8 * j) * N_ + n0 + tx;
        tile[ty + 8 * j][tx] = rb[idx] * hb[idx];
    }
    __syncthreads();
#pragma unroll
    for (int j = 0; j < 4; ++j)
        ot[(size_t)(n0 + ty + 8 * j) * C_ + c0 + tx] = __float2half_rn(tile[tx][ty + 8 * j]);
}

// ---------------------------------------------------------------------------
// Prep + elementwise kernels
// ---------------------------------------------------------------------------
__global__ void k_wt16(const float* __restrict__ w, __half* __restrict__ wt) {
    size_t i = (size_t)blockIdx.x * 256 + threadIdx.x;
    if (i >= WTSZ) return;
    int ci  = (int)(i % (2 * C_));
    int co  = (int)((i / (2 * C_)) % C_);
    int tap = (int)(i / ((size_t)C_ * 2 * C_));
    wt[i] = __float2half_rn(w[((size_t)co * (2 * C_) + ci) * 9 + tap]);
}

__global__ void k_wru16(const float* __restrict__ wr, const float* __restrict__ wu,
                        __half* __restrict__ o) {
    size_t i = (size_t)blockIdx.x * 256 + threadIdx.x;
    size_t half = (size_t)C_ * 2 * C_;
    if (i < half) o[i] = __float2half_rn(wr[i]);
    else if (i < 2 * half) o[i] = __float2half_rn(wu[i - half]);
}

__global__ void k_wc16(const float* __restrict__ w, __half* __restrict__ o) {
    size_t i = (size_t)blockIdx.x * 256 + threadIdx.x;
    if (i < (size_t)C_ * 2 * C_) o[i] = __float2half_rn(w[i]);
}

__global__ void k_init(const float* __restrict__ a, const float* __restrict__ b,
                       const float* __restrict__ c) {
    size_t i = ((size_t)blockIdx.x * 256 + threadIdx.x) * 4;
    *(float4*)(g_ex + i) = *(const float4*)(a + i);
    *(float4*)(g_q  + i) = *(const float4*)(b + i);
    *(float4*)(g_q1 + i) = *(const float4*)(c + i);
}

__global__ void k_gruout(float* __restrict__ h, const float* __restrict__ u,
                         const float* __restrict__ c) {
    size_t i = ((size_t)blockIdx.x * 256 + threadIdx.x) * 4;
    float4 hv = *(float4*)(h + i);
    float4 uv = *(const float4*)(u + i);
    float4 cv = *(const float4*)(c + i);
    hv.x = hv.x * (1.f - uv.x) + cv.x * uv.x;
    hv.y = hv.y * (1.f - uv.y) + cv.y * uv.y;
    hv.z = hv.z * (1.f - uv.z) + cv.z * uv.z;
    hv.w = hv.w * (1.f - uv.w) + cv.w * uv.w;
    *(float4*)(h + i) = hv;
}

// ---------------------------------------------------------------------------
// Host orchestration
// ---------------------------------------------------------------------------
extern "C" void kernel_launch(void* const* d_in, const int* in_sizes, int n_in,
                              void* d_out, int out_size) {
    const float* in1      = (const float*)d_in[0];
    const float* in2      = (const float*)d_in[1];
    const float* in3      = (const float*)d_in[2];
    const float* w_fusion = (const float*)d_in[3];
    const float* b_fusion = (const float*)d_in[4];
    const float* w_out    = (const float*)d_in[5];
    const float* b_out    = (const float*)d_in[6];
    const float* w_reset  = (const float*)d_in[7];
    const float* b_reset  = (const float*)d_in[8];
    const float* w_update = (const float*)d_in[9];
    const float* b_update = (const float*)d_in[10];
    const float* w_cand   = (const float*)d_in[11];
    const float* b_cand   = (const float*)d_in[12];
    float* out = (float*)d_out;

    cudaFuncSetAttribute(k_scores,   cudaFuncAttributeMaxDynamicSharedMemorySize, SMEM_DYN);
    cudaFuncSetAttribute(k_attmm,    cudaFuncAttributeMaxDynamicSharedMemorySize, SMEM_DYN);
    cudaFuncSetAttribute(k_gemmRU,   cudaFuncAttributeMaxDynamicSharedMemorySize, SMEM_DYN);
    cudaFuncSetAttribute(k_gemmCAND, cudaFuncAttributeMaxDynamicSharedMemorySize, SMEM_DYN);
    cudaFuncSetAttribute(k_conv3,    cudaFuncAttributeMaxDynamicSharedMemorySize, SMEM_DYN);

    float *S1, *S2, *S3, *St, *O1, *O2, *a, *ex, *q, *q1, *r, *u, *c;
    __half *P16, *ex16, *q16, *q116, *exT, *qT, *q1T;
    __half *O1T, *O2T, *aT, *rhT, *in1T, *in2T, *in3T;
    __half *wf16, *wo16, *wru16, *wc16;
    cudaGetSymbolAddress((void**)&S1,   g_S1);
    cudaGetSymbolAddress((void**)&S2,   g_S2);
    cudaGetSymbolAddress((void**)&S3,   g_S3);
    cudaGetSymbolAddress((void**)&St,   g_St);
    cudaGetSymbolAddress((void**)&O1,   g_O1);
    cudaGetSymbolAddress((void**)&O2,   g_O2);
    cudaGetSymbolAddress((void**)&a,    g_a);
    cudaGetSymbolAddress((void**)&ex,   g_ex);
    cudaGetSymbolAddress((void**)&q,    g_q);
    cudaGetSymbolAddress((void**)&q1,   g_q1);
    cudaGetSymbolAddress((void**)&r,    g_r);
    cudaGetSymbolAddress((void**)&u,    g_u);
    cudaGetSymbolAddress((void**)&c,    g_c);
    cudaGetSymbolAddress((void**)&P16,  g_P16);
    cudaGetSymbolAddress((void**)&ex16, g_ex16);
    cudaGetSymbolAddress((void**)&q16,  g_q16);
    cudaGetSymbolAddress((void**)&q116, g_q116);
    cudaGetSymbolAddress((void**)&exT,  g_exT16);
    cudaGetSymbolAddress((void**)&qT,   g_qT16);
    cudaGetSymbolAddress((void**)&q1T,  g_q1T16);
    cudaGetSymbolAddress((void**)&O1T,  g_O1T16);
    cudaGetSymbolAddress((void**)&O2T,  g_O2T16);
    cudaGetSymbolAddress((void**)&aT,   g_aT16);
    cudaGetSymbolAddress((void**)&rhT,  g_rhT16);
    cudaGetSymbolAddress((void**)&in1T, g_in1T16);
    cudaGetSymbolAddress((void**)&in2T, g_in2T16);
    cudaGetSymbolAddress((void**)&in3T, g_in3T16);
    cudaGetSymbolAddress((void**)&wf16, g_wf16);
    cudaGetSymbolAddress((void**)&wo16, g_wo16);
    cudaGetSymbolAddress((void**)&wru16, g_wru16);
    cudaGetSymbolAddress((void**)&wc16, g_wc16);

    const int EWG = (int)(TSZ / 4 / 256);
    const int WTG = (int)((WTSZ + 255) / 256);
    const int RUG = (int)(((size_t)2 * C_ * 2 * C_ + 255) / 256);
    const int WCG = (int)(((size_t)C_ * 2 * C_ + 255) / 256);

    k_init<<<EWG, 256>>>(in1, in2, in3);
    k_wt16<<<WTG, 256>>>(w_fusion, wf16);
    k_wt16<<<WTG, 256>>>(w_out, wo16);
    k_wru16<<<RUG, 256>>>(w_reset, w_update, wru16);
    k_wc16<<<WCG, 256>>>(w_cand, wc16);

    dim3 trG(32, 16, B_), trB(32, 8);
    dim3 trSG(32, 32, B_);
    k_trh<<<trG, trB>>>(in1, in1T);
    k_trh<<<trG, trB>>>(in2, in2T);
    k_trh<<<trG, trB>>>(in3, in3T);

    dim3 gSC(8, 8, B_);     // scores / RU (M=1024)
    dim3 gAT(8, 4, B_);     // attmm / conv3 / cand
    const int SMG = B_ * N_;

    float*  hs[3] = {ex, q, q1};
    __half* hT[3] = {exT, qT, q1T};

    for (int round = 0; round < 5; ++round) {
        k_tr2<<<trG, trB>>>(ex, ex16, exT);
        k_tr2<<<trG, trB>>>(q,  q16,  qT);
        k_tr2<<<trG, trB>>>(q1, q116, q1T);

        // 3 unique logits matrices; transposes provide the other 3
        k_scores<<<gSC, 256, SMEM_DYN>>>(exT, qT,  S1);   // att(ex,q) rows
        k_scores<<<gSC, 256, SMEM_DYN>>>(exT, q1T, S2);   // att(ex,q1) rows
        k_scores<<<gSC, 256, SMEM_DYN>>>(qT,  q1T, S3);   // att(q,q1) rows

        for (int s = 0; s < 3; ++s) {
            // first partner probs source
            if (s == 0)      { k_softmaxP<<<SMG, 256>>>(S1, P16); }
            else if (s == 1) { k_trS<<<trSG, trB>>>(S1, St); k_softmaxP<<<SMG, 256>>>(St, P16); }
            else             { k_trS<<<trSG, trB>>>(S2, St); k_softmaxP<<<SMG, 256>>>(St, P16); }
            __half* o1n = (s == 0) ? q16 : ex16;
            k_attmm<<<gAT, 256, SMEM_DYN>>>(o1n, P16, O1);

            // second partner probs source
            if (s == 0)      { k_softmaxP<<<SMG, 256>>>(S2, P16); }
            else if (s == 1) { k_softmaxP<<<SMG, 256>>>(S3, P16); }
            else             { k_trS<<<trSG, trB>>>(S3, St); k_softmaxP<<<SMG, 256>>>(St, P16); }
            __half* o2n = (s == 2) ? q16 : q116;
            k_attmm<<<gAT, 256, SMEM_DYN>>>(o2n, P16, O2);

            k_trh<<<trG, trB>>>(O1, O1T);
            k_trh<<<trG, trB>>>(O2, O2T);
            k_conv3<<<gAT, 256, SMEM_DYN>>>(wf16, O1T, O2T, b_fusion, a);

            k_trh<<<trG, trB>>>(a, aT);
            k_gemmRU<<<gSC, 256, SMEM_DYN>>>(wru16, aT, hT[s], b_reset, b_update, r, u);
            k_rh<<<trG, trB>>>(r, hs[s], rhT);
            k_gemmCAND<<<gAT, 256, SMEM_DYN>>>(wc16, aT, rhT, b_cand, c);
            k_gruout<<<EWG, 256>>>(hs[s], u, c);
        }
    }

    // final output convs: B = [stateT ; inT]
    k_trh<<<trG, trB>>>(ex, exT);
    k_trh<<<trG, trB>>>(q,  qT);
    k_trh<<<trG, trB>>>(q1, q1T);
    k_conv3<<<gAT, 256, SMEM_DYN>>>(wo16, exT, in1T, b_out, out);
    k_conv3<<<gAT, 256, SMEM_DYN>>>(wo16, qT,  in2T, b_out, out + TSZ);
    k_conv3<<<gAT, 256, SMEM_DYN>>>(wo16, q1T, in3T, b_out, out + 2 * TSZ);
}

// round 9
// speedup vs baseline: 1.0706x; 1.0706x over previous
#include <cuda_runtime.h>
#include <cuda_fp16.h>
#include <math.h>
#include <stdint.h>

// ---------------------------------------------------------------------------
// Problem constants
// ---------------------------------------------------------------------------
#define B_  16
#define C_  512
#define N_  1024
#define HW  32
#define SPITCH 12                      // smem row stride in u32 (48B) - conflict-free
#define NSTG 4                         // pipeline stages
#define STGSZ (128 * SPITCH * 4)       // 6144 B per matrix per stage
#define SMEM_DYN (2 * NSTG * STGSZ)    // 49152 B

static constexpr size_t TSZ  = (size_t)B_ * C_ * N_;
static constexpr size_t SSZ  = (size_t)B_ * N_ * N_;
static constexpr size_t WTSZ = (size_t)9 * C_ * (2 * C_);

// ---------------------------------------------------------------------------
// Scratch (static device globals; no allocation anywhere)
// ---------------------------------------------------------------------------
__device__ float g_S [SSZ];
__device__ float g_ex[TSZ], g_q [TSZ], g_q1[TSZ];
__device__ float g_r [TSZ], g_u [TSZ], g_c [TSZ];

__device__ __align__(128) __half g_P16  [SSZ];                     // probs [n][m]
// double-buffered state mirrors
__device__ __align__(128) __half g_ex16a [TSZ], g_q16a [TSZ], g_q116a[TSZ]; // [c][n]
__device__ __align__(128) __half g_ex16b [TSZ], g_q16b [TSZ], g_q116b[TSZ];
__device__ __align__(128) __half g_exT16a[TSZ], g_qT16a[TSZ], g_q1T16a[TSZ];// [n][c]
__device__ __align__(128) __half g_exT16b[TSZ], g_qT16b[TSZ], g_q1T16b[TSZ];
__device__ __align__(128) __half g_O1T16[TSZ], g_O2T16[TSZ];       // [p][c]
__device__ __align__(128) __half g_aT16 [TSZ], g_rhT16[TSZ];       // [p][c]
__device__ __align__(128) __half g_in1T16[TSZ], g_in2T16[TSZ], g_in3T16[TSZ];
__device__ __align__(128) __half g_wf16[WTSZ], g_wo16[WTSZ];       // [tap][co][ci]
__device__ __align__(128) __half g_wru16[(size_t)(2 * C_) * (2 * C_)];
__device__ __align__(128) __half g_wc16 [(size_t)C_ * (2 * C_)];

// ---------------------------------------------------------------------------
// cp.async helpers
// ---------------------------------------------------------------------------
__device__ __forceinline__ void cpa16(uint32_t dst, const void* src, uint32_t sz) {
    asm volatile("cp.async.ca.shared.global [%0], [%1], 16, %2;"
                 :: "r"(dst), "l"(src), "r"(sz) : "memory");
}
#define CP_COMMIT() asm volatile("cp.async.commit_group;" ::: "memory")
#define CP_WAIT2()  asm volatile("cp.async.wait_group 2;" ::: "memory")

// ---------------------------------------------------------------------------
// fp16 mma.sync microkernel: 4 warps, warp tile 64x64, block tile 128x128
// (R7 configuration — proven fastest)
// ---------------------------------------------------------------------------
__device__ __forceinline__ void mma16(float* d, const uint32_t* a, uint32_t b0, uint32_t b1) {
    asm volatile(
        "mma.sync.aligned.m16n8k16.row.col.f32.f16.f16.f32 "
        "{%0,%1,%2,%3}, {%4,%5,%6,%7}, {%8,%9}, {%0,%1,%2,%3};\n"
        : "+f"(d[0]), "+f"(d[1]), "+f"(d[2]), "+f"(d[3])
        : "r"(a[0]), "r"(a[1]), "r"(a[2]), "r"(a[3]), "r"(b0), "r"(b1));
}

__device__ __forceinline__ void ldsm4(uint32_t* r, uint32_t addr) {
    asm volatile(
        "ldmatrix.sync.aligned.m8n8.x4.shared.b16 {%0,%1,%2,%3}, [%4];"
        : "=r"(r[0]), "=r"(r[1]), "=r"(r[2]), "=r"(r[3]) : "r"(addr));
}

__device__ __forceinline__ void compute16(uint32_t aB, uint32_t bB,
                                          float (*acc)[8][4], int wm, int wn,
                                          int lane) {
    int lr = lane & 15;
    uint32_t lc = (uint32_t)(lane >> 4) * 16;
    uint32_t a[4][4], b[4][4];
#pragma unroll
    for (int mt = 0; mt < 4; ++mt)
        ldsm4(a[mt], aB + (uint32_t)(wm + mt * 16 + lr) * (SPITCH * 4) + lc);
#pragma unroll
    for (int np = 0; np < 4; ++np)
        ldsm4(b[np], bB + (uint32_t)(wn + np * 16 + lr) * (SPITCH * 4) + lc);
#pragma unroll
    for (int mt = 0; mt < 4; ++mt)
#pragma unroll
        for (int np = 0; np < 4; ++np) {
            mma16(acc[mt][2 * np],     a[mt], b[np][0], b[np][2]);
            mma16(acc[mt][2 * np + 1], a[mt], b[np][1], b[np][3]);
        }
}

#define ZERO_ACC(acc)                                       \
    float acc[4][8][4];                                     \
    _Pragma("unroll")                                       \
    for (int i_ = 0; i_ < 4; ++i_)                          \
        _Pragma("unroll")                                   \
        for (int j_ = 0; j_ < 8; ++j_)                      \
            _Pragma("unroll")                               \
            for (int v_ = 0; v_ < 4; ++v_) acc[i_][j_][v_] = 0.f;

#define GEMM_PRE()                                                           \
    extern __shared__ __align__(1024) char dsm[];                            \
    int t = threadIdx.x, lane = t & 31, wid = t >> 5;                        \
    int wm = (wid & 1) * 64, wn = (wid >> 1) * 64;                           \
    int g = lane >> 2, tg = lane & 3;                                        \
    uint32_t sAs = (uint32_t)__cvta_generic_to_shared(dsm);                  \
    uint32_t sBs = sAs + NSTG * STGSZ;                                       \
    (void)g; (void)tg;

#define GEMM_PIPE(KI, ISSUE, acc)                                            \
    for (int s_ = 0; s_ < 3; ++s_) { ISSUE(s_); CP_COMMIT(); }               \
    for (int it_ = 0; it_ < (KI); ++it_) {                                   \
        CP_WAIT2();                                                          \
        __syncthreads();                                                     \
        compute16(sAs + (it_ & 3) * STGSZ, sBs + (it_ & 3) * STGSZ,          \
                  acc, wm, wn, lane);                                        \
        if (it_ + 3 < (KI)) ISSUE(it_ + 3);                                  \
        CP_COMMIT();                                                         \
    }

// ---------------------------------------------------------------------------
// k_scores: S[b,n,m] = sum_c ET[n,c] * QT[m,c].  grid (8,8,16), 128 thr
// ---------------------------------------------------------------------------
__global__ void __launch_bounds__(128, 2) k_scores(const __half* __restrict__ ET,
                                                   const __half* __restrict__ QT,
                                                   float* __restrict__ S) {
    GEMM_PRE();
    int b = blockIdx.z;
    int n0 = blockIdx.y * 128, m0 = blockIdx.x * 128;
    const __half* arow = ET + (size_t)b * N_ * C_ + (size_t)(n0 + t) * C_;
    const __half* brow = QT + (size_t)b * N_ * C_ + (size_t)(m0 + t) * C_;
    float* Sb = S + (size_t)b * N_ * N_;

    auto issue = [&](int it) {
        uint32_t da = sAs + (it & 3) * STGSZ + t * 48;
        uint32_t db = sBs + (it & 3) * STGSZ + t * 48;
        const __half* pa = arow + it * 16;
        const __half* pb = brow + it * 16;
        cpa16(da, pa, 16); cpa16(da + 16, pa + 8, 16);
        cpa16(db, pb, 16); cpa16(db + 16, pb + 8, 16);
    };

    ZERO_ACC(acc);
    GEMM_PIPE(C_ / 16, issue, acc);

#pragma unroll
    for (int mt = 0; mt < 4; ++mt)
#pragma unroll
        for (int nt = 0; nt < 8; ++nt) {
            int row = n0 + wm + mt * 16 + g;
            int col = m0 + wn + nt * 8 + tg * 2;
            *(float2*)(Sb + (size_t)row * N_ + col)       = make_float2(acc[mt][nt][0], acc[mt][nt][1]);
            *(float2*)(Sb + (size_t)(row + 8) * N_ + col) = make_float2(acc[mt][nt][2], acc[mt][nt][3]);
        }
}

// ---------------------------------------------------------------------------
// Row softmax: read fp32 scores, write fp16 probs. grid B_*N_, 256 thr
// ---------------------------------------------------------------------------
__global__ void __launch_bounds__(256) k_softmaxP(const float* __restrict__ S,
                                                  __half* __restrict__ P) {
    const float* row = S + (size_t)blockIdx.x * N_;
    __half*      out = P + (size_t)blockIdx.x * N_;
    int t = threadIdx.x;
    float4 v = *(const float4*)(row + 4 * t);
    __shared__ float red[8];

    float m = fmaxf(fmaxf(v.x, v.y), fmaxf(v.z, v.w));
#pragma unroll
    for (int o = 16; o; o >>= 1) m = fmaxf(m, __shfl_xor_sync(0xffffffffu, m, o));
    if ((t & 31) == 0) red[t >> 5] = m;
    __syncthreads();
    float mx = red[0];
#pragma unroll
    for (int i = 1; i < 8; ++i) mx = fmaxf(mx, red[i]);
    __syncthreads();

    v.x = __expf(v.x - mx); v.y = __expf(v.y - mx);
    v.z = __expf(v.z - mx); v.w = __expf(v.w - mx);
    float s = v.x + v.y + v.z + v.w;
#pragma unroll
    for (int o = 16; o; o >>= 1) s += __shfl_xor_sync(0xffffffffu, s, o);
    if ((t & 31) == 0) red[t >> 5] = s;
    __syncthreads();
    float tot = red[0];
#pragma unroll
    for (int i = 1; i < 8; ++i) tot += red[i];
    float inv = 1.f / tot;

    *(__half2*)(out + 4 * t)     = __floats2half2_rn(v.x * inv, v.y * inv);
    *(__half2*)(out + 4 * t + 2) = __floats2half2_rn(v.z * inv, v.w * inv);
}

// ---------------------------------------------------------------------------
// k_attmmT: OT[b,n,c] = sum_m P[n,m] * Q16[c,m] — fp16 transposed output,
// directly consumable by conv3T.  grid (4,8,16), 128 thr
// ---------------------------------------------------------------------------
__global__ void __launch_bounds__(128, 2) k_attmmT(const __half* __restrict__ P,
                                                   const __half* __restrict__ Q16,
                                                   __half* __restrict__ OT) {
    GEMM_PRE();
    int b = blockIdx.z;
    int n0 = blockIdx.y * 128, c0 = blockIdx.x * 128;
    const __half* arow = P   + (size_t)b * N_ * N_ + (size_t)(n0 + t) * N_;
    const __half* brow = Q16 + (size_t)b * C_ * N_ + (size_t)(c0 + t) * N_;
    __half* Ob = OT + (size_t)b * N_ * C_;

    auto issue = [&](int it) {
        uint32_t da = sAs + (it & 3) * STGSZ + t * 48;
        uint32_t db = sBs + (it & 3) * STGSZ + t * 48;
        const __half* pa = arow + it * 16;
        const __half* pb = brow + it * 16;
        cpa16(da, pa, 16); cpa16(da + 16, pa + 8, 16);
        cpa16(db, pb, 16); cpa16(db + 16, pb + 8, 16);
    };

    ZERO_ACC(acc);
    GEMM_PIPE(N_ / 16, issue, acc);

#pragma unroll
    for (int mt = 0; mt < 4; ++mt)
#pragma unroll
        for (int nt = 0; nt < 8; ++nt) {
            int row = n0 + wm + mt * 16 + g;
            int col = c0 + wn + nt * 8 + tg * 2;
            *(__half2*)(Ob + (size_t)row * C_ + col) =
                __floats2half2_rn(acc[mt][nt][0], acc[mt][nt][1]);
            *(__half2*)(Ob + (size_t)(row + 8) * C_ + col) =
                __floats2half2_rn(acc[mt][nt][2], acc[mt][nt][3]);
        }
}

// ---------------------------------------------------------------------------
// k_conv3T: fusion conv, output TRANSPOSED fp16 aT[p][co].
// A = shifted pixel rows of [p][c] fp16 inputs, B = weight rows.
// grid (4,8,16), 128 thr
// ---------------------------------------------------------------------------
__global__ void __launch_bounds__(128, 2) k_conv3T(const __half* __restrict__ Wt,
                                                   const __half* __restrict__ x0T,
                                                   const __half* __restrict__ x1T,
                                                   const float* __restrict__ bias,
                                                   __half* __restrict__ YT) {
    GEMM_PRE();
    int b = blockIdx.z;
    int p0 = blockIdx.y * 128, cb0 = blockIdx.x * 128;
    const __half* x0b = x0T + (size_t)b * N_ * C_;
    const __half* x1b = x1T + (size_t)b * N_ * C_;
    __half* Yb = YT + (size_t)b * N_ * C_;

    int p = p0 + t;
    int py = p >> 5, px = p & 31;

    auto issue = [&](int it) {
        int tap = it >> 6, ci0 = (it & 63) * 16;
        uint32_t da = sAs + (it & 3) * STGSZ + t * 48;
        uint32_t db = sBs + (it & 3) * STGSZ + t * 48;
        // A: shifted pixel row
        int dy = tap / 3 - 1, dx = tap % 3 - 1;
        int y = py + dy, x = px + dx;
        bool ok = ((unsigned)y < HW) && ((unsigned)x < HW);
        int pp = ok ? (y * HW + x) : 0;
        const __half* pa = (ci0 < C_) ? (x0b + (size_t)pp * C_ + ci0)
                                      : (x1b + (size_t)pp * C_ + ci0 - C_);
        uint32_t sz = ok ? 16u : 0u;
        cpa16(da, pa, sz); cpa16(da + 16, pa + 8, sz);
        // B: weight row
        const __half* pb = Wt + ((size_t)tap * C_ + cb0 + t) * (2 * C_) + ci0;
        cpa16(db, pb, 16); cpa16(db + 16, pb + 8, 16);
    };

    ZERO_ACC(acc);
    GEMM_PIPE(9 * (2 * C_) / 16, issue, acc);

#pragma unroll
    for (int mt = 0; mt < 4; ++mt)
#pragma unroll
        for (int nt = 0; nt < 8; ++nt) {
            int row = p0 + wm + mt * 16 + g;     // pixel
            int col = cb0 + wn + nt * 8 + tg * 2; // out channel
            float b0 = bias[col], b1 = bias[col + 1];
            *(__half2*)(Yb + (size_t)row * C_ + col) =
                __floats2half2_rn(acc[mt][nt][0] + b0, acc[mt][nt][1] + b1);
            *(__half2*)(Yb + (size_t)(row + 8) * C_ + col) =
                __floats2half2_rn(acc[mt][nt][2] + b0, acc[mt][nt][3] + b1);
        }
}

// ---------------------------------------------------------------------------
// k_gemmRU: fused reset+update GEMM, M=1024, B=[xT;hT]. grid (8,8,16), 128 thr
// ---------------------------------------------------------------------------
__global__ void __launch_bounds__(128, 2) k_gemmRU(const __half* __restrict__ Wru,
                                                   const __half* __restrict__ xT,
                                                   const __half* __restrict__ hT,
                                                   const float* __restrict__ b_r,
                                                   const float* __restrict__ b_u,
                                                   float* __restrict__ R,
                                                   float* __restrict__ U) {
    GEMM_PRE();
    int b = blockIdx.z;
    int co0 = blockIdx.y * 128, p0 = blockIdx.x * 128;
    const __half* arow = Wru + (size_t)(co0 + t) * (2 * C_);
    const __half* xrow = xT + (size_t)b * N_ * C_ + (size_t)(p0 + t) * C_;
    const __half* hrow = hT + (size_t)b * N_ * C_ + (size_t)(p0 + t) * C_;

    auto issue = [&](int it) {
        uint32_t da = sAs + (it & 3) * STGSZ + t * 48;
        uint32_t db = sBs + (it & 3) * STGSZ + t * 48;
        int ci0 = it * 16;
        const __half* pa = arow + ci0;
        const __half* pb = (ci0 < C_) ? (xrow + ci0) : (hrow + ci0 - C_);
        cpa16(da, pa, 16); cpa16(da + 16, pa + 8, 16);
        cpa16(db, pb, 16); cpa16(db + 16, pb + 8, 16);
    };

    ZERO_ACC(acc);
    GEMM_PIPE((2 * C_) / 16, issue, acc);

    bool isR = co0 < C_;
    float* dst = (isR ? R : U) + (size_t)b * C_ * N_;
    int rbase = isR ? co0 : (co0 - C_);
    const float* bias = isR ? b_r : b_u;
#pragma unroll
    for (int mt = 0; mt < 4; ++mt)
#pragma unroll
        for (int nt = 0; nt < 8; ++nt) {
            int row = rbase + wm + mt * 16 + g;
            int col = p0 + wn + nt * 8 + tg * 2;
            float bv0 = bias[row], bv1 = bias[row + 8];
            float o0 = 1.f / (1.f + __expf(-(acc[mt][nt][0] + bv0)));
            float o1 = 1.f / (1.f + __expf(-(acc[mt][nt][1] + bv0)));
            float o2 = 1.f / (1.f + __expf(-(acc[mt][nt][2] + bv1)));
            float o3 = 1.f / (1.f + __expf(-(acc[mt][nt][3] + bv1)));
            *(float2*)(dst + (size_t)row * N_ + col)       = make_float2(o0, o1);
            *(float2*)(dst + (size_t)(row + 8) * N_ + col) = make_float2(o2, o3);
        }
}

// ---------------------------------------------------------------------------
// k_gemmCAND: c = tanh(Wc @ [x ; r*h] + b).  grid (8,4,16), 128 thr
// ---------------------------------------------------------------------------
__global__ void __launch_bounds__(128, 2) k_gemmCAND(const __half* __restrict__ Wc,
                                                     const __half* __restrict__ xT,
                                                     const __half* __restrict__ rhT,
                                                     const float* __restrict__ bias,
                                                     float* __restrict__ Y) {
    GEMM_PRE();
    int b = blockIdx.z;
    int co0 = blockIdx.y * 128, p0 = blockIdx.x * 128;
    const __half* arow  = Wc + (size_t)(co0 + t) * (2 * C_);
    const __half* xrow  = xT  + (size_t)b * N_ * C_ + (size_t)(p0 + t) * C_;
    const __half* rhrow = rhT + (size_t)b * N_ * C_ + (size_t)(p0 + t) * C_;
    float* Yb = Y + (size_t)b * C_ * N_;

    auto issue = [&](int it) {
        uint32_t da = sAs + (it & 3) * STGSZ + t * 48;
        uint32_t db = sBs + (it & 3) * STGSZ + t * 48;
        int ci0 = it * 16;
        const __half* pa = arow + ci0;
        const __half* pb = (ci0 < C_) ? (xrow + ci0) : (rhrow + ci0 - C_);
        cpa16(da, pa, 16); cpa16(da + 16, pa + 8, 16);
        cpa16(db, pb, 16); cpa16(db + 16, pb + 8, 16);
    };

    ZERO_ACC(acc);
    GEMM_PIPE((2 * C_) / 16, issue, acc);

#pragma unroll
    for (int mt = 0; mt < 4; ++mt)
#pragma unroll
        for (int nt = 0; nt < 8; ++nt) {
            int row = co0 + wm + mt * 16 + g;
            int col = p0 + wn + nt * 8 + tg * 2;
            float bv0 = bias[row], bv1 = bias[row + 8];
            *(float2*)(Yb + (size_t)row * N_ + col) =
                make_float2(tanhf(acc[mt][nt][0] + bv0), tanhf(acc[mt][nt][1] + bv0));
            *(float2*)(Yb + (size_t)(row + 8) * N_ + col) =
                make_float2(tanhf(acc[mt][nt][2] + bv1), tanhf(acc[mt][nt][3] + bv1));
        }
}

// ---------------------------------------------------------------------------
// k_conv3: final output conv (fp32 [co][p] output). grid (8,4,16), 128 thr
// ---------------------------------------------------------------------------
__global__ void __launch_bounds__(128, 2) k_conv3(const __half* __restrict__ Wt,
                                                  const __half* __restrict__ x0T,
                                                  const __half* __restrict__ x1T,
                                                  const float* __restrict__ bias,
                                                  float* __restrict__ Y) {
    GEMM_PRE();
    int b = blockIdx.z;
    int co0 = blockIdx.y * 128, p0 = blockIdx.x * 128;
    const __half* x0b = x0T + (size_t)b * N_ * C_;
    const __half* x1b = x1T + (size_t)b * N_ * C_;
    float* Yb = Y + (size_t)b * C_ * N_;

    int p = p0 + t;
    int py = p >> 5, px = p & 31;

    auto issue = [&](int it) {
        int tap = it >> 6, ci0 = (it & 63) * 16;
        uint32_t da = sAs + (it & 3) * STGSZ + t * 48;
        uint32_t db = sBs + (it & 3) * STGSZ + t * 48;
        const __half* pa = Wt + ((size_t)tap * C_ + co0 + t) * (2 * C_) + ci0;
        cpa16(da, pa, 16); cpa16(da + 16, pa + 8, 16);

        int dy = tap / 3 - 1, dx = tap % 3 - 1;
        int y = py + dy, x = px + dx;
        bool ok = ((unsigned)y < HW) && ((unsigned)x < HW);
        int pp = ok ? (y * HW + x) : 0;
        const __half* pb = (ci0 < C_) ? (x0b + (size_t)pp * C_ + ci0)
                                      : (x1b + (size_t)pp * C_ + ci0 - C_);
        uint32_t sz = ok ? 16u : 0u;
        cpa16(db, pb, sz); cpa16(db + 16, pb + 8, sz);
    };

    ZERO_ACC(acc);
    GEMM_PIPE(9 * (2 * C_) / 16, issue, acc);

#pragma unroll
    for (int mt = 0; mt < 4; ++mt)
#pragma unroll
        for (int nt = 0; nt < 8; ++nt) {
            int row = co0 + wm + mt * 16 + g;
            int col = p0 + wn + nt * 8 + tg * 2;
            float bv0 = bias[row], bv1 = bias[row + 8];
            *(float2*)(Yb + (size_t)row * N_ + col)       = make_float2(acc[mt][nt][0] + bv0, acc[mt][nt][1] + bv0);
            *(float2*)(Yb + (size_t)(row + 8) * N_ + col) = make_float2(acc[mt][nt][2] + bv1, acc[mt][nt][3] + bv1);
        }
}

// ---------------------------------------------------------------------------
// k_gruout2: h = h(1-u)+cu, also emits fp16 mirrors [c][n] and [n][c].
// grid (32,16,B_), block (32,8)
// ---------------------------------------------------------------------------
__global__ void k_gruout2(float* __restrict__ h, const float* __restrict__ u,
                          const float* __restrict__ c,
                          __half* __restrict__ h16o, __half* __restrict__ hTo) {
    __shared__ float tile[32][33];
    int b = blockIdx.z;
    float*       hb = h + (size_t)b * C_ * N_;
    const float* ub = u + (size_t)b * C_ * N_;
    const float* cb = c + (size_t)b * C_ * N_;
    __half* on = h16o + (size_t)b * C_ * N_;
    __half* ot = hTo  + (size_t)b * N_ * C_;
    int n0 = blockIdx.x * 32, c0 = blockIdx.y * 32;
    int tx = threadIdx.x, ty = threadIdx.y;
#pragma unroll
    for (int j = 0; j < 4; ++j) {
        size_t idx = (size_t)(c0 + ty + 8 * j) * N_ + n0 + tx;
        float hv = hb[idx] * (1.f - ub[idx]) + cb[idx] * ub[idx];
        hb[idx] = hv;
        on[idx] = __float2half_rn(hv);
        tile[ty + 8 * j][tx] = hv;
    }
    __syncthreads();
#pragma unroll
    for (int j = 0; j < 4; ++j)
        ot[(size_t)(n0 + ty + 8 * j) * C_ + c0 + tx] = __float2half_rn(tile[tx][ty + 8 * j]);
}

// ---------------------------------------------------------------------------
// Transpose/convert helpers
// ---------------------------------------------------------------------------
__global__ void k_tr2(const float* __restrict__ in, __half* __restrict__ outN,
                      __half* __restrict__ outT) {
    __shared__ float tile[32][33];
    int b = blockIdx.z;
    const float* ib = in + (size_t)b * C_ * N_;
    __half* on = outN + (size_t)b * C_ * N_;
    __half* ot = outT + (size_t)b * N_ * C_;
    int n0 = blockIdx.x * 32, c0 = blockIdx.y * 32;
    int tx = threadIdx.x, ty = threadIdx.y;
#pragma unroll
    for (int j = 0; j < 4; ++j) {
        float v = ib[(size_t)(c0 + ty + 8 * j) * N_ + n0 + tx];
        tile[ty + 8 * j][tx] = v;
        on[(size_t)(c0 + ty + 8 * j) * N_ + n0 + tx] = __float2half_rn(v);
    }
    __syncthreads();
#pragma unroll
    for (int j = 0; j < 4; ++j)
        ot[(size_t)(n0 + ty + 8 * j) * C_ + c0 + tx] = __float2half_rn(tile[tx][ty + 8 * j]);
}

__global__ void k_trh(const float* __restrict__ in, __half* __restrict__ outT) {
    __shared__ float tile[32][33];
    int b = blockIdx.z;
    const float* ib = in + (size_t)b * C_ * N_;
    __half* ot = outT + (size_t)b * N_ * C_;
    int n0 = blockIdx.x * 32, c0 = blockIdx.y * 32;
    int tx = threadIdx.x, ty = threadIdx.y;
#pragma unroll
    for (int j = 0; j < 4; ++j)
        tile[ty + 8 * j][tx] = ib[(size_t)(c0 + ty + 8 * j) * N_ + n0 + tx];
    __syncthreads();
#pragma unroll
    for (int j = 0; j < 4; ++j)
        ot[(size_t)(n0 + ty + 8 * j) * C_ + c0 + tx] = __float2half_rn(tile[tx][ty + 8 * j]);
}

__global__ void k_rh(const float* __restrict__ r, const float* __restrict__ h,
                     __half* __restrict__ outT) {
    __shared__ float tile[32][33];
    int b = blockIdx.z;
    const float* rb = r + (size_t)b * C_ * N_;
    const float* hb = h + (size_t)b * C_ * N_;
    __half* ot = outT + (size_t)b * N_ * C_;
    int n0 = blockIdx.x * 32, c0 = blockIdx.y * 32;
    int tx = threadIdx.x, ty = threadIdx.y;
#pragma unroll
    for (int j = 0; j < 4; ++j) {
        size_t idx = (size_t)(c0 + ty + 8 * j) * N_ + n0 + tx;
        tile[ty + 8 * j][tx] = rb[idx] * hb[idx];
    }
    __syncthreads();
#pragma unroll
    for (int j = 0; j < 4; ++j)
        ot[(size_t)(n0 + ty + 8 * j) * C_ + c0 + tx] = __float2half_rn(tile[tx][ty + 8 * j]);
}

// ---------------------------------------------------------------------------
// Prep kernels
// ---------------------------------------------------------------------------
__global__ void k_wt16(const float* __restrict__ w, __half* __restrict__ wt) {
    size_t i = (size_t)blockIdx.x * 256 + threadIdx.x;
    if (i >= WTSZ) return;
    int ci  = (int)(i % (2 * C_));
    int co  = (int)((i / (2 * C_)) % C_);
    int tap = (int)(i / ((size_t)C_ * 2 * C_));
    wt[i] = __float2half_rn(w[((size_t)co * (2 * C_) + ci) * 9 + tap]);
}

__global__ void k_wru16(const float* __restrict__ wr, const float* __restrict__ wu,
                        __half* __restrict__ o) {
    size_t i = (size_t)blockIdx.x * 256 + threadIdx.x;
    size_t half = (size_t)C_ * 2 * C_;
    if (i < half) o[i] = __float2half_rn(wr[i]);
    else if (i < 2 * half) o[i] = __float2half_rn(wu[i - half]);
}

__global__ void k_wc16(const float* __restrict__ w, __half* __restrict__ o) {
    size_t i = (size_t)blockIdx.x * 256 + threadIdx.x;
    if (i < (size_t)C_ * 2 * C_) o[i] = __float2half_rn(w[i]);
}

__global__ void k_init(const float* __restrict__ a, const float* __restrict__ b,
                       const float* __restrict__ c) {
    size_t i = ((size_t)blockIdx.x * 256 + threadIdx.x) * 4;
    *(float4*)(g_ex + i) = *(const float4*)(a + i);
    *(float4*)(g_q  + i) = *(const float4*)(b + i);
    *(float4*)(g_q1 + i) = *(const float4*)(c + i);
}

// ---------------------------------------------------------------------------
// Host orchestration
// ---------------------------------------------------------------------------
extern "C" void kernel_launch(void* const* d_in, const int* in_sizes, int n_in,
                              void* d_out, int out_size) {
    const float* in1      = (const float*)d_in[0];
    const float* in2      = (const float*)d_in[1];
    const float* in3      = (const float*)d_in[2];
    const float* w_fusion = (const float*)d_in[3];
    const float* b_fusion = (const float*)d_in[4];
    const float* w_out    = (const float*)d_in[5];
    const float* b_out    = (const float*)d_in[6];
    const float* w_reset  = (const float*)d_in[7];
    const float* b_reset  = (const float*)d_in[8];
    const float* w_update = (const float*)d_in[9];
    const float* b_update = (const float*)d_in[10];
    const float* w_cand   = (const float*)d_in[11];
    const float* b_cand   = (const float*)d_in[12];
    float* out = (float*)d_out;

    cudaFuncSetAttribute(k_scores,   cudaFuncAttributeMaxDynamicSharedMemorySize, SMEM_DYN);
    cudaFuncSetAttribute(k_attmmT,   cudaFuncAttributeMaxDynamicSharedMemorySize, SMEM_DYN);
    cudaFuncSetAttribute(k_conv3T,   cudaFuncAttributeMaxDynamicSharedMemorySize, SMEM_DYN);
    cudaFuncSetAttribute(k_gemmRU,   cudaFuncAttributeMaxDynamicSharedMemorySize, SMEM_DYN);
    cudaFuncSetAttribute(k_gemmCAND, cudaFuncAttributeMaxDynamicSharedMemorySize, SMEM_DYN);
    cudaFuncSetAttribute(k_conv3,    cudaFuncAttributeMaxDynamicSharedMemorySize, SMEM_DYN);

    float *S, *ex, *q, *q1, *r, *u, *c;
    __half *P16, *O1T, *O2T, *aT, *rhT, *in1T, *in2T, *in3T;
    __half *wf16, *wo16, *wru16, *wc16;
    __half *m16a[3], *m16b[3], *mTa[3], *mTb[3];
    cudaGetSymbolAddress((void**)&S,    g_S);
    cudaGetSymbolAddress((void**)&ex,   g_ex);
    cudaGetSymbolAddress((void**)&q,    g_q);
    cudaGetSymbolAddress((void**)&q1,   g_q1);
    cudaGetSymbolAddress((void**)&r,    g_r);
    cudaGetSymbolAddress((void**)&u,    g_u);
    cudaGetSymbolAddress((void**)&c,    g_c);
    cudaGetSymbolAddress((void**)&P16,  g_P16);
    cudaGetSymbolAddress((void**)&O1T,  g_O1T16);
    cudaGetSymbolAddress((void**)&O2T,  g_O2T16);
    cudaGetSymbolAddress((void**)&aT,   g_aT16);
    cudaGetSymbolAddress((void**)&rhT,  g_rhT16);
    cudaGetSymbolAddress((void**)&in1T, g_in1T16);
    cudaGetSymbolAddress((void**)&in2T, g_in2T16);
    cudaGetSymbolAddress((void**)&in3T, g_in3T16);
    cudaGetSymbolAddress((void**)&wf16, g_wf16);
    cudaGetSymbolAddress((void**)&wo16, g_wo16);
    cudaGetSymbolAddress((void**)&wru16, g_wru16);
    cudaGetSymbolAddress((void**)&wc16, g_wc16);
    cudaGetSymbolAddress((void**)&m16a[0], g_ex16a);
    cudaGetSymbolAddress((void**)&m16a[1], g_q16a);
    cudaGetSymbolAddress((void**)&m16a[2], g_q116a);
    cudaGetSymbolAddress((void**)&m16b[0], g_ex16b);
    cudaGetSymbolAddress((void**)&m16b[1], g_q16b);
    cudaGetSymbolAddress((void**)&m16b[2], g_q116b);
    cudaGetSymbolAddress((void**)&mTa[0], g_exT16a);
    cudaGetSymbolAddress((void**)&mTa[1], g_qT16a);
    cudaGetSymbolAddress((void**)&mTa[2], g_q1T16a);
    cudaGetSymbolAddress((void**)&mTb[0], g_exT16b);
    cudaGetSymbolAddress((void**)&mTb[1], g_qT16b);
    cudaGetSymbolAddress((void**)&mTb[2], g_q1T16b);

    const int EWG = (int)(TSZ / 4 / 256);
    const int WTG = (int)((WTSZ + 255) / 256);
    const int RUG = (int)(((size_t)2 * C_ * 2 * C_ + 255) / 256);
    const int WCG = (int)(((size_t)C_ * 2 * C_ + 255) / 256);

    k_init<<<EWG, 256>>>(in1, in2, in3);
    k_wt16<<<WTG, 256>>>(w_fusion, wf16);
    k_wt16<<<WTG, 256>>>(w_out, wo16);
    k_wru16<<<RUG, 256>>>(w_reset, w_update, wru16);
    k_wc16<<<WCG, 256>>>(w_cand, wc16);

    dim3 trG(32, 16, B_), trB(32, 8);
    k_trh<<<trG, trB>>>(in1, in1T);
    k_trh<<<trG, trB>>>(in2, in2T);
    k_trh<<<trG, trB>>>(in3, in3T);

    // initial mirrors (from input states)
    k_tr2<<<trG, trB>>>(ex, m16a[0], mTa[0]);
    k_tr2<<<trG, trB>>>(q,  m16a[1], mTa[1]);
    k_tr2<<<trG, trB>>>(q1, m16a[2], mTa[2]);

    dim3 gSC(8, 8, B_);     // scores / RU (M=1024)
    dim3 gT (4, 8, B_);     // attmmT / conv3T (output [n/p][c])
    dim3 gCD(8, 4, B_);     // cand
    dim3 gFC(8, 4, B_);     // final conv (fp32 [co][p])
    const int SMG = B_ * N_;

    float* hs[3] = {ex, q, q1};
    __half** cur16 = m16a;  __half** curT = mTa;
    __half** nw16  = m16b;  __half** nwT  = mTb;

    for (int round = 0; round < 5; ++round) {
        for (int s = 0; s < 3; ++s) {
            __half* meT = curT[s];
            __half* p1T = (s == 0) ? curT[1] : curT[0];
            __half* p1n = (s == 0) ? cur16[1] : cur16[0];
            __half* p2T = (s == 2) ? curT[1] : curT[2];
            __half* p2n = (s == 2) ? cur16[1] : cur16[2];

            k_scores<<<gSC, 128, SMEM_DYN>>>(meT, p1T, S);
            k_softmaxP<<<SMG, 256>>>(S, P16);
            k_attmmT<<<gT, 128, SMEM_DYN>>>(P16, p1n, O1T);

            k_scores<<<gSC, 128, SMEM_DYN>>>(meT, p2T, S);
            k_softmaxP<<<SMG, 256>>>(S, P16);
            k_attmmT<<<gT, 128, SMEM_DYN>>>(P16, p2n, O2T);

            k_conv3T<<<gT, 128, SMEM_DYN>>>(wf16, O1T, O2T, b_fusion, aT);

            k_gemmRU<<<gSC, 128, SMEM_DYN>>>(wru16, aT, curT[s], b_reset, b_update, r, u);
            k_rh<<<trG, trB>>>(r, hs[s], rhT);
            k_gemmCAND<<<gCD, 128, SMEM_DYN>>>(wc16, aT, rhT, b_cand, c);
            k_gruout2<<<trG, trB>>>(hs[s], u, c, nw16[s], nwT[s]);
        }
        // swap mirror buffers (new mirrors become current for next round)
        __half** t16 = cur16; cur16 = nw16; nw16 = t16;
        __half** tT  = curT;  curT  = nwT;  nwT  = tT;
    }

    // final output convs: B = [stateT ; inT]
    k_conv3<<<gFC, 128, SMEM_DYN>>>(wo16, curT[0], in1T, b_out, out);
    k_conv3<<<gFC, 128, SMEM_DYN>>>(wo16, curT[1], in2T, b_out, out + TSZ);
    k_conv3<<<gFC, 128, SMEM_DYN>>>(wo16, curT[2], in3T, b_out, out + 2 * TSZ);
}

// round 10
// speedup vs baseline: 1.1615x; 1.0849x over previous
#include <cuda_runtime.h>
#include <cuda_fp16.h>
#include <math.h>
#include <stdint.h>

// ---------------------------------------------------------------------------
// Problem constants
// ---------------------------------------------------------------------------
#define B_  16
#define C_  512
#define N_  1024
#define HW  32
#define SPITCH 12                      // smem row stride in u32 (48B) - conflict-free
#define NSTG 4                         // pipeline stages
#define STGSZ (128 * SPITCH * 4)       // 6144 B per matrix per stage
#define SMEM_DYN (2 * NSTG * STGSZ)    // 49152 B

static constexpr size_t TSZ  = (size_t)B_ * C_ * N_;
static constexpr size_t SSZ  = (size_t)B_ * N_ * N_;
static constexpr size_t WTSZ = (size_t)9 * C_ * (2 * C_);

// ---------------------------------------------------------------------------
// Scratch (static device globals; no allocation anywhere)
// ---------------------------------------------------------------------------
__device__ float g_S [6 * SSZ];                    // 6 logits matrices
__device__ float g_ex[TSZ], g_q [TSZ], g_q1[TSZ];  // fp32 states
__device__ float g_u [3 * TSZ], g_c [3 * TSZ];     // per-state gates

__device__ __align__(128) __half g_P16[6 * SSZ];   // 6 prob matrices [n][m]
__device__ __align__(128) __half g_OT [6 * TSZ];   // attention outputs [p][c]
__device__ __align__(128) __half g_aT [3 * TSZ];   // fusion outputs [p][c]
__device__ __align__(128) __half g_rhT[3 * TSZ];   // r*h [p][c]
// double-buffered state mirrors
__device__ __align__(128) __half g_ex16a [TSZ], g_q16a [TSZ], g_q116a[TSZ]; // [c][n]
__device__ __align__(128) __half g_ex16b [TSZ], g_q16b [TSZ], g_q116b[TSZ];
__device__ __align__(128) __half g_exT16a[TSZ], g_qT16a[TSZ], g_q1T16a[TSZ];// [n][c]
__device__ __align__(128) __half g_exT16b[TSZ], g_qT16b[TSZ], g_q1T16b[TSZ];
__device__ __align__(128) __half g_in1T16[TSZ], g_in2T16[TSZ], g_in3T16[TSZ];
__device__ __align__(128) __half g_wf16[WTSZ], g_wo16[WTSZ];       // [tap][co][ci]
__device__ __align__(128) __half g_wru16[(size_t)(2 * C_) * (2 * C_)];
__device__ __align__(128) __half g_wc16 [(size_t)C_ * (2 * C_)];

// ---------------------------------------------------------------------------
// Helpers
// ---------------------------------------------------------------------------
__device__ __forceinline__ const __half* sel3(int i, const __half* a,
                                              const __half* b, const __half* c) {
    return i == 0 ? a : (i == 1 ? b : c);
}
__device__ __forceinline__ __half* sel3h(int i, __half* a, __half* b, __half* c) {
    return i == 0 ? a : (i == 1 ? b : c);
}
__device__ __forceinline__ float* sel3f(int i, float* a, float* b, float* c) {
    return i == 0 ? a : (i == 1 ? b : c);
}
__device__ __forceinline__ const float* sel3cf(int i, const float* a,
                                               const float* b, const float* c) {
    return i == 0 ? a : (i == 1 ? b : c);
}
// pair table: j in 0..5 -> (A = j>>1, B = pairB(j)); states 0=ex,1=q,2=q1
__device__ __forceinline__ int pairB(int j) {
    switch (j) { case 0: return 1; case 1: return 2; case 2: return 0;
                 case 3: return 2; case 4: return 0; default: return 1; }
}
__device__ __forceinline__ float sigm(float x) { return 1.f / (1.f + __expf(-x)); }

__device__ __forceinline__ void cpa16(uint32_t dst, const void* src, uint32_t sz) {
    asm volatile("cp.async.ca.shared.global [%0], [%1], 16, %2;"
                 :: "r"(dst), "l"(src), "r"(sz) : "memory");
}
#define CP_COMMIT() asm volatile("cp.async.commit_group;" ::: "memory")
#define CP_WAIT2()  asm volatile("cp.async.wait_group 2;" ::: "memory")

// ---------------------------------------------------------------------------
// fp16 mma.sync microkernel: 4 warps, warp tile 64x64, block tile 128x128
// ---------------------------------------------------------------------------
__device__ __forceinline__ void mma16(float* d, const uint32_t* a, uint32_t b0, uint32_t b1) {
    asm volatile(
        "mma.sync.aligned.m16n8k16.row.col.f32.f16.f16.f32 "
        "{%0,%1,%2,%3}, {%4,%5,%6,%7}, {%8,%9}, {%0,%1,%2,%3};\n"
        : "+f"(d[0]), "+f"(d[1]), "+f"(d[2]), "+f"(d[3])
        : "r"(a[0]), "r"(a[1]), "r"(a[2]), "r"(a[3]), "r"(b0), "r"(b1));
}

__device__ __forceinline__ void ldsm4(uint32_t* r, uint32_t addr) {
    asm volatile(
        "ldmatrix.sync.aligned.m8n8.x4.shared.b16 {%0,%1,%2,%3}, [%4];"
        : "=r"(r[0]), "=r"(r[1]), "=r"(r[2]), "=r"(r[3]) : "r"(addr));
}

__device__ __forceinline__ void compute16(uint32_t aB, uint32_t bB,
                                          float (*acc)[8][4], int wm, int wn,
                                          int lane) {
    int lr = lane & 15;
    uint32_t lc = (uint32_t)(lane >> 4) * 16;
    uint32_t a[4][4], b[4][4];
#pragma unroll
    for (int mt = 0; mt < 4; ++mt)
        ldsm4(a[mt], aB + (uint32_t)(wm + mt * 16 + lr) * (SPITCH * 4) + lc);
#pragma unroll
    for (int np = 0; np < 4; ++np)
        ldsm4(b[np], bB + (uint32_t)(wn + np * 16 + lr) * (SPITCH * 4) + lc);
#pragma unroll
    for (int mt = 0; mt < 4; ++mt)
#pragma unroll
        for (int np = 0; np < 4; ++np) {
            mma16(acc[mt][2 * np],     a[mt], b[np][0], b[np][2]);
            mma16(acc[mt][2 * np + 1], a[mt], b[np][1], b[np][3]);
        }
}

#define ZERO_ACC(acc)                                       \
    float acc[4][8][4];                                     \
    _Pragma("unroll")                                       \
    for (int i_ = 0; i_ < 4; ++i_)                          \
        _Pragma("unroll")                                   \
        for (int j_ = 0; j_ < 8; ++j_)                      \
            _Pragma("unroll")                               \
            for (int v_ = 0; v_ < 4; ++v_) acc[i_][j_][v_] = 0.f;

#define GEMM_PRE()                                                           \
    extern __shared__ __align__(1024) char dsm[];                            \
    int t = threadIdx.x, lane = t & 31, wid = t >> 5;                        \
    int wm = (wid & 1) * 64, wn = (wid >> 1) * 64;                           \
    int g = lane >> 2, tg = lane & 3;                                        \
    uint32_t sAs = (uint32_t)__cvta_generic_to_shared(dsm);                  \
    uint32_t sBs = sAs + NSTG * STGSZ;                                       \
    (void)g; (void)tg;

#define GEMM_PIPE(KI, ISSUE, acc)                                            \
    for (int s_ = 0; s_ < 3; ++s_) { ISSUE(s_); CP_COMMIT(); }               \
    for (int it_ = 0; it_ < (KI); ++it_) {                                   \
        CP_WAIT2();                                                          \
        __syncthreads();                                                     \
        compute16(sAs + (it_ & 3) * STGSZ, sBs + (it_ & 3) * STGSZ,          \
                  acc, wm, wn, lane);                                        \
        if (it_ + 3 < (KI)) ISSUE(it_ + 3);                                  \
        CP_COMMIT();                                                         \
    }

// ---------------------------------------------------------------------------
// k_scores_all: 6 logits GEMMs. grid (8,8,96): j = z>>4 pair, b = z&15
// ---------------------------------------------------------------------------
__global__ void __launch_bounds__(128, 2) k_scores_all(
        const __half* __restrict__ exT, const __half* __restrict__ qT,
        const __half* __restrict__ q1T, float* __restrict__ S) {
    GEMM_PRE();
    int z = blockIdx.z, j = z >> 4, b = z & 15;
    const __half* A  = sel3(j >> 1,   exT, qT, q1T);
    const __half* Bm = sel3(pairB(j), exT, qT, q1T);
    int n0 = blockIdx.y * 128, m0 = blockIdx.x * 128;
    const __half* arow = A  + (size_t)b * N_ * C_ + (size_t)(n0 + t) * C_;
    const __half* brow = Bm + (size_t)b * N_ * C_ + (size_t)(m0 + t) * C_;
    float* Sb = S + (size_t)j * SSZ + (size_t)b * N_ * N_;

    auto issue = [&](int it) {
        uint32_t da = sAs + (it & 3) * STGSZ + t * 48;
        uint32_t db = sBs + (it & 3) * STGSZ + t * 48;
        const __half* pa = arow + it * 16;
        const __half* pb = brow + it * 16;
        cpa16(da, pa, 16); cpa16(da + 16, pa + 8, 16);
        cpa16(db, pb, 16); cpa16(db + 16, pb + 8, 16);
    };

    ZERO_ACC(acc);
    GEMM_PIPE(C_ / 16, issue, acc);

#pragma unroll
    for (int mt = 0; mt < 4; ++mt)
#pragma unroll
        for (int nt = 0; nt < 8; ++nt) {
            int row = n0 + wm + mt * 16 + g;
            int col = m0 + wn + nt * 8 + tg * 2;
            *(float2*)(Sb + (size_t)row * N_ + col)       = make_float2(acc[mt][nt][0], acc[mt][nt][1]);
            *(float2*)(Sb + (size_t)(row + 8) * N_ + col) = make_float2(acc[mt][nt][2], acc[mt][nt][3]);
        }
}

// ---------------------------------------------------------------------------
// Row softmax over all 6 matrices. grid 6*B_*N_, 256 thr
// ---------------------------------------------------------------------------
__global__ void __launch_bounds__(256) k_softmax_all(const float* __restrict__ S,
                                                     __half* __restrict__ P) {
    const float* row = S + (size_t)blockIdx.x * N_;
    __half*      out = P + (size_t)blockIdx.x * N_;
    int t = threadIdx.x;
    float4 v = *(const float4*)(row + 4 * t);
    __shared__ float red[8];

    float m = fmaxf(fmaxf(v.x, v.y), fmaxf(v.z, v.w));
#pragma unroll
    for (int o = 16; o; o >>= 1) m = fmaxf(m, __shfl_xor_sync(0xffffffffu, m, o));
    if ((t & 31) == 0) red[t >> 5] = m;
    __syncthreads();
    float mx = red[0];
#pragma unroll
    for (int i = 1; i < 8; ++i) mx = fmaxf(mx, red[i]);
    __syncthreads();

    v.x = __expf(v.x - mx); v.y = __expf(v.y - mx);
    v.z = __expf(v.z - mx); v.w = __expf(v.w - mx);
    float s = v.x + v.y + v.z + v.w;
#pragma unroll
    for (int o = 16; o; o >>= 1) s += __shfl_xor_sync(0xffffffffu, s, o);
    if ((t & 31) == 0) red[t >> 5] = s;
    __syncthreads();
    float tot = red[0];
#pragma unroll
    for (int i = 1; i < 8; ++i) tot += red[i];
    float inv = 1.f / tot;

    *(__half2*)(out + 4 * t)     = __floats2half2_rn(v.x * inv, v.y * inv);
    *(__half2*)(out + 4 * t + 2) = __floats2half2_rn(v.z * inv, v.w * inv);
}

// ---------------------------------------------------------------------------
// k_attmmT_all: 6 attention-output GEMMs, fp16 [p][c] output.
// grid (4,8,96): j = z>>4, b = z&15
// ---------------------------------------------------------------------------
__global__ void __launch_bounds__(128, 2) k_attmmT_all(
        const __half* __restrict__ P,
        const __half* __restrict__ ex16, const __half* __restrict__ q16,
        const __half* __restrict__ q116, __half* __restrict__ OT) {
    GEMM_PRE();
    int z = blockIdx.z, j = z >> 4, b = z & 15;
    const __half* Bn = sel3(pairB(j), ex16, q16, q116);
    int n0 = blockIdx.y * 128, c0 = blockIdx.x * 128;
    const __half* arow = P  + (size_t)j * SSZ + (size_t)b * N_ * N_ + (size_t)(n0 + t) * N_;
    const __half* brow = Bn + (size_t)b * C_ * N_ + (size_t)(c0 + t) * N_;
    __half* Ob = OT + (size_t)j * TSZ + (size_t)b * N_ * C_;

    auto issue = [&](int it) {
        uint32_t da = sAs + (it & 3) * STGSZ + t * 48;
        uint32_t db = sBs + (it & 3) * STGSZ + t * 48;
        const __half* pa = arow + it * 16;
        const __half* pb = brow + it * 16;
        cpa16(da, pa, 16); cpa16(da + 16, pa + 8, 16);
        cpa16(db, pb, 16); cpa16(db + 16, pb + 8, 16);
    };

    ZERO_ACC(acc);
    GEMM_PIPE(N_ / 16, issue, acc);

#pragma unroll
    for (int mt = 0; mt < 4; ++mt)
#pragma unroll
        for (int nt = 0; nt < 8; ++nt) {
            int row = n0 + wm + mt * 16 + g;
            int col = c0 + wn + nt * 8 + tg * 2;
            *(__half2*)(Ob + (size_t)row * C_ + col) =
                __floats2half2_rn(acc[mt][nt][0], acc[mt][nt][1]);
            *(__half2*)(Ob + (size_t)(row + 8) * C_ + col) =
                __floats2half2_rn(acc[mt][nt][2], acc[mt][nt][3]);
        }
}

// ---------------------------------------------------------------------------
// k_conv3T_all: 3 fusion convs, output fp16 aT[p][co]. grid (4,8,48)
// ---------------------------------------------------------------------------
__global__ void __launch_bounds__(128, 2) k_conv3T_all(
        const __half* __restrict__ Wt, const __half* __restrict__ OT,
        const float* __restrict__ bias, __half* __restrict__ aT) {
    GEMM_PRE();
    int z = blockIdx.z, j = z >> 4, b = z & 15;
    int p0 = blockIdx.y * 128, cb0 = blockIdx.x * 128;
    const __half* x0b = OT + (size_t)(2 * j)     * TSZ + (size_t)b * N_ * C_;
    const __half* x1b = OT + (size_t)(2 * j + 1) * TSZ + (size_t)b * N_ * C_;
    __half* Yb = aT + (size_t)j * TSZ + (size_t)b * N_ * C_;

    int p = p0 + t;
    int py = p >> 5, px = p & 31;

    auto issue = [&](int it) {
        int tap = it >> 6, ci0 = (it & 63) * 16;
        uint32_t da = sAs + (it & 3) * STGSZ + t * 48;
        uint32_t db = sBs + (it & 3) * STGSZ + t * 48;
        int dy = tap / 3 - 1, dx = tap % 3 - 1;
        int y = py + dy, x = px + dx;
        bool ok = ((unsigned)y < HW) && ((unsigned)x < HW);
        int pp = ok ? (y * HW + x) : 0;
        const __half* pa = (ci0 < C_) ? (x0b + (size_t)pp * C_ + ci0)
                                      : (x1b + (size_t)pp * C_ + ci0 - C_);
        uint32_t sz = ok ? 16u : 0u;
        cpa16(da, pa, sz); cpa16(da + 16, pa + 8, sz);
        const __half* pb = Wt + ((size_t)tap * C_ + cb0 + t) * (2 * C_) + ci0;
        cpa16(db, pb, 16); cpa16(db + 16, pb + 8, 16);
    };

    ZERO_ACC(acc);
    GEMM_PIPE(9 * (2 * C_) / 16, issue, acc);

#pragma unroll
    for (int mt = 0; mt < 4; ++mt)
#pragma unroll
        for (int nt = 0; nt < 8; ++nt) {
            int row = p0 + wm + mt * 16 + g;
            int col = cb0 + wn + nt * 8 + tg * 2;
            float b0 = bias[col], b1 = bias[col + 1];
            *(__half2*)(Yb + (size_t)row * C_ + col) =
                __floats2half2_rn(acc[mt][nt][0] + b0, acc[mt][nt][1] + b1);
            *(__half2*)(Yb + (size_t)(row + 8) * C_ + col) =
                __floats2half2_rn(acc[mt][nt][2] + b0, acc[mt][nt][3] + b1);
        }
}

// ---------------------------------------------------------------------------
// k_gemmRU_all: 3 fused reset+update GEMMs. M=1024 (r|u). grid (8,8,48)
// r-half epilogue computes r*h (fp32 state) and writes fp16 rhT[p][c] directly.
// ---------------------------------------------------------------------------
__global__ void __launch_bounds__(128, 2) k_gemmRU_all(
        const __half* __restrict__ Wru, const __half* __restrict__ aT,
        const __half* __restrict__ exT, const __half* __restrict__ qT,
        const __half* __restrict__ q1T,
        float* __restrict__ hex, float* __restrict__ hq, float* __restrict__ hq1,
        const float* __restrict__ b_r, const float* __restrict__ b_u,
        __half* __restrict__ rhT, float* __restrict__ u) {
    GEMM_PRE();
    int z = blockIdx.z, j = z >> 4, b = z & 15;
    int co0 = blockIdx.y * 128, p0 = blockIdx.x * 128;
    const __half* hTj = sel3(j, exT, qT, q1T);
    const __half* arow = Wru + (size_t)(co0 + t) * (2 * C_);
    const __half* xrow = aT + (size_t)j * TSZ + (size_t)b * N_ * C_ + (size_t)(p0 + t) * C_;
    const __half* hrow = hTj + (size_t)b * N_ * C_ + (size_t)(p0 + t) * C_;

    auto issue = [&](int it) {
        uint32_t da = sAs + (it & 3) * STGSZ + t * 48;
        uint32_t db = sBs + (it & 3) * STGSZ + t * 48;
        int ci0 = it * 16;
        const __half* pa = arow + ci0;
        const __half* pb = (ci0 < C_) ? (xrow + ci0) : (hrow + ci0 - C_);
        cpa16(da, pa, 16); cpa16(da + 16, pa + 8, 16);
        cpa16(db, pb, 16); cpa16(db + 16, pb + 8, 16);
    };

    ZERO_ACC(acc);
    GEMM_PIPE((2 * C_) / 16, issue, acc);

    bool isR = co0 < C_;
    if (isR) {
        const float* hb = sel3cf(j, hex, hq, hq1) + (size_t)b * C_ * N_;
        __half* rh = rhT + (size_t)j * TSZ + (size_t)b * N_ * C_;
#pragma unroll
        for (int mt = 0; mt < 4; ++mt)
#pragma unroll
            for (int nt = 0; nt < 8; ++nt) {
                int row = co0 + wm + mt * 16 + g;
                int col = p0 + wn + nt * 8 + tg * 2;
                float bv0 = b_r[row], bv1 = b_r[row + 8];
                float o0 = sigm(acc[mt][nt][0] + bv0) * hb[(size_t)row * N_ + col];
                float o1 = sigm(acc[mt][nt][1] + bv0) * hb[(size_t)row * N_ + col + 1];
                float o2 = sigm(acc[mt][nt][2] + bv1) * hb[(size_t)(row + 8) * N_ + col];
                float o3 = sigm(acc[mt][nt][3] + bv1) * hb[(size_t)(row + 8) * N_ + col + 1];
                rh[(size_t)col * C_ + row]           = __float2half_rn(o0);
                rh[(size_t)(col + 1) * C_ + row]     = __float2half_rn(o1);
                rh[(size_t)col * C_ + row + 8]       = __float2half_rn(o2);
                rh[(size_t)(col + 1) * C_ + row + 8] = __float2half_rn(o3);
            }
    } else {
        int rbase = co0 - C_;
        float* ub = u + (size_t)j * TSZ + (size_t)b * C_ * N_;
#pragma unroll
        for (int mt = 0; mt < 4; ++mt)
#pragma unroll
            for (int nt = 0; nt < 8; ++nt) {
                int row = rbase + wm + mt * 16 + g;
                int col = p0 + wn + nt * 8 + tg * 2;
                float bv0 = b_u[row], bv1 = b_u[row + 8];
                *(float2*)(ub + (size_t)row * N_ + col) =
                    make_float2(sigm(acc[mt][nt][0] + bv0), sigm(acc[mt][nt][1] + bv0));
                *(float2*)(ub + (size_t)(row + 8) * N_ + col) =
                    make_float2(sigm(acc[mt][nt][2] + bv1), sigm(acc[mt][nt][3] + bv1));
            }
    }
}

// ---------------------------------------------------------------------------
// k_gemmCAND_all: 3 candidate GEMMs, c = tanh(Wc@[x;r*h]+b). grid (8,4,48)
// ---------------------------------------------------------------------------
__global__ void __launch_bounds__(128, 2) k_gemmCAND_all(
        const __half* __restrict__ Wc, const __half* __restrict__ aT,
        const __half* __restrict__ rhT, const float* __restrict__ bias,
        float* __restrict__ cbuf) {
    GEMM_PRE();
    int z = blockIdx.z, j = z >> 4, b = z & 15;
    int co0 = blockIdx.y * 128, p0 = blockIdx.x * 128;
    const __half* arow  = Wc + (size_t)(co0 + t) * (2 * C_);
    const __half* xrow  = aT  + (size_t)j * TSZ + (size_t)b * N_ * C_ + (size_t)(p0 + t) * C_;
    const __half* rhrow = rhT + (size_t)j * TSZ + (size_t)b * N_ * C_ + (size_t)(p0 + t) * C_;
    float* Yb = cbuf + (size_t)j * TSZ + (size_t)b * C_ * N_;

    auto issue = [&](int it) {
        uint32_t da = sAs + (it & 3) * STGSZ + t * 48;
        uint32_t db = sBs + (it & 3) * STGSZ + t * 48;
        int ci0 = it * 16;
        const __half* pa = arow + ci0;
        const __half* pb = (ci0 < C_) ? (xrow + ci0) : (rhrow + ci0 - C_);
        cpa16(da, pa, 16); cpa16(da + 16, pa + 8, 16);
        cpa16(db, pb, 16); cpa16(db + 16, pb + 8, 16);
    };

    ZERO_ACC(acc);
    GEMM_PIPE((2 * C_) / 16, issue, acc);

#pragma unroll
    for (int mt = 0; mt < 4; ++mt)
#pragma unroll
        for (int nt = 0; nt < 8; ++nt) {
            int row = co0 + wm + mt * 16 + g;
            int col = p0 + wn + nt * 8 + tg * 2;
            float bv0 = bias[row], bv1 = bias[row + 8];
            *(float2*)(Yb + (size_t)row * N_ + col) =
                make_float2(tanhf(acc[mt][nt][0] + bv0), tanhf(acc[mt][nt][1] + bv0));
            *(float2*)(Yb + (size_t)(row + 8) * N_ + col) =
                make_float2(tanhf(acc[mt][nt][2] + bv1), tanhf(acc[mt][nt][3] + bv1));
        }
}

// ---------------------------------------------------------------------------
// k_conv3_all: final 3 output convs (fp32 [co][p]). grid (8,4,48)
// ---------------------------------------------------------------------------
__global__ void __launch_bounds__(128, 2) k_conv3_all(
        const __half* __restrict__ Wt,
        const __half* __restrict__ exT, const __half* __restrict__ qT,
        const __half* __restrict__ q1T,
        const __half* __restrict__ in1T, const __half* __restrict__ in2T,
        const __half* __restrict__ in3T,
        const float* __restrict__ bias, float* __restrict__ Y) {
    GEMM_PRE();
    int z = blockIdx.z, s = z >> 4, b = z & 15;
    int co0 = blockIdx.y * 128, p0 = blockIdx.x * 128;
    const __half* x0b = sel3(s, exT, qT, q1T)    + (size_t)b * N_ * C_;
    const __half* x1b = sel3(s, in1T, in2T, in3T) + (size_t)b * N_ * C_;
    float* Yb = Y + (size_t)s * TSZ + (size_t)b * C_ * N_;

    int p = p0 + t;
    int py = p >> 5, px = p & 31;

    auto issue = [&](int it) {
        int tap = it >> 6, ci0 = (it & 63) * 16;
        uint32_t da = sAs + (it & 3) * STGSZ + t * 48;
        uint32_t db = sBs + (it & 3) * STGSZ + t * 48;
        const __half* pa = Wt + ((size_t)tap * C_ + co0 + t) * (2 * C_) + ci0;
        cpa16(da, pa, 16); cpa16(da + 16, pa + 8, 16);

        int dy = tap / 3 - 1, dx = tap % 3 - 1;
        int y = py + dy, x = px + dx;
        bool ok = ((unsigned)y < HW) && ((unsigned)x < HW);
        int pp = ok ? (y * HW + x) : 0;
        const __half* pb = (ci0 < C_) ? (x0b + (size_t)pp * C_ + ci0)
                                      : (x1b + (size_t)pp * C_ + ci0 - C_);
        uint32_t sz = ok ? 16u : 0u;
        cpa16(db, pb, sz); cpa16(db + 16, pb + 8, sz);
    };

    ZERO_ACC(acc);
    GEMM_PIPE(9 * (2 * C_) / 16, issue, acc);

#pragma unroll
    for (int mt = 0; mt < 4; ++mt)
#pragma unroll
        for (int nt = 0; nt < 8; ++nt) {
            int row = co0 + wm + mt * 16 + g;
            int col = p0 + wn + nt * 8 + tg * 2;
            float bv0 = bias[row], bv1 = bias[row + 8];
            *(float2*)(Yb + (size_t)row * N_ + col)       = make_float2(acc[mt][nt][0] + bv0, acc[mt][nt][1] + bv0);
            *(float2*)(Yb + (size_t)(row + 8) * N_ + col) = make_float2(acc[mt][nt][2] + bv1, acc[mt][nt][3] + bv1);
        }
}

// ---------------------------------------------------------------------------
// k_gruout_all: h = h(1-u)+cu for 3 states, emits fp16 mirrors. grid (32,16,48)
// ---------------------------------------------------------------------------
__global__ void k_gruout_all(
        float* __restrict__ hex, float* __restrict__ hq, float* __restrict__ hq1,
        const float* __restrict__ u, const float* __restrict__ c,
        __half* __restrict__ n16_0, __half* __restrict__ n16_1, __half* __restrict__ n16_2,
        __half* __restrict__ nT_0, __half* __restrict__ nT_1, __half* __restrict__ nT_2) {
    __shared__ float tile[32][33];
    int z = blockIdx.z, s = z >> 4, b = z & 15;
    float*       hb = sel3f(s, hex, hq, hq1) + (size_t)b * C_ * N_;
    const float* ub = u + (size_t)s * TSZ + (size_t)b * C_ * N_;
    const float* cb = c + (size_t)s * TSZ + (size_t)b * C_ * N_;
    __half* on = sel3h(s, n16_0, n16_1, n16_2) + (size_t)b * C_ * N_;
    __half* ot = sel3h(s, nT_0, nT_1, nT_2)    + (size_t)b * N_ * C_;
    int n0 = blockIdx.x * 32, c0 = blockIdx.y * 32;
    int tx = threadIdx.x, ty = threadIdx.y;
#pragma unroll
    for (int j = 0; j < 4; ++j) {
        size_t idx = (size_t)(c0 + ty + 8 * j) * N_ + n0 + tx;
        float hv = hb[idx] * (1.f - ub[idx]) + cb[idx] * ub[idx];
        hb[idx] = hv;
        on[idx] = __float2half_rn(hv);
        tile[ty + 8 * j][tx] = hv;
    }
    __syncthreads();
#pragma unroll
    for (int j = 0; j < 4; ++j)
        ot[(size_t)(n0 + ty + 8 * j) * C_ + c0 + tx] = __float2half_rn(tile[tx][ty + 8 * j]);
}

// ---------------------------------------------------------------------------
// Prep kernels (fused)
// ---------------------------------------------------------------------------
__global__ void k_prep_w(const float* __restrict__ wf, const float* __restrict__ wo,
                         __half* __restrict__ of, __half* __restrict__ oo) {
    size_t i = (size_t)blockIdx.x * 256 + threadIdx.x;
    if (i >= WTSZ) return;
    const float* w = blockIdx.y ? wo : wf;
    __half* o = blockIdx.y ? oo : of;
    int ci  = (int)(i % (2 * C_));
    int co  = (int)((i / (2 * C_)) % C_);
    int tap = (int)(i / ((size_t)C_ * 2 * C_));
    o[i] = __float2half_rn(w[((size_t)co * (2 * C_) + ci) * 9 + tap]);
}

__global__ void k_prep_g(const float* __restrict__ wr, const float* __restrict__ wu,
                         const float* __restrict__ wc,
                         __half* __restrict__ oru, __half* __restrict__ oc) {
    size_t i = (size_t)blockIdx.x * 256 + threadIdx.x;
    size_t half = (size_t)C_ * 2 * C_;
    if (i < half) oru[i] = __float2half_rn(wr[i]);
    else if (i < 2 * half) oru[i] = __float2half_rn(wu[i - half]);
    else if (i < 3 * half) oc[i - 2 * half] = __float2half_rn(wc[i - 2 * half]);
}

// z<48: init states + mirrors from inputs; z>=48: input T mirrors
__global__ void k_premirror(
        const float* __restrict__ in1, const float* __restrict__ in2,
        const float* __restrict__ in3,
        float* __restrict__ hex, float* __restrict__ hq, float* __restrict__ hq1,
        __half* __restrict__ m16_0, __half* __restrict__ m16_1, __half* __restrict__ m16_2,
        __half* __restrict__ mT_0, __half* __restrict__ mT_1, __half* __restrict__ mT_2,
        __half* __restrict__ i1T, __half* __restrict__ i2T, __half* __restrict__ i3T) {
    __shared__ float tile[32][33];
    int z = blockIdx.z;
    int tx = threadIdx.x, ty = threadIdx.y;
    int n0 = blockIdx.x * 32, c0 = blockIdx.y * 32;
    if (z < 48) {
        int s = z >> 4, b = z & 15;
        const float* ib = sel3cf(s, in1, in2, in3) + (size_t)b * C_ * N_;
        float* hb = sel3f(s, hex, hq, hq1) + (size_t)b * C_ * N_;
        __half* on = sel3h(s, m16_0, m16_1, m16_2) + (size_t)b * C_ * N_;
        __half* ot = sel3h(s, mT_0, mT_1, mT_2)    + (size_t)b * N_ * C_;
#pragma unroll
        for (int j = 0; j < 4; ++j) {
            size_t idx = (size_t)(c0 + ty + 8 * j) * N_ + n0 + tx;
            float v = ib[idx];
            hb[idx] = v;
            on[idx] = __float2half_rn(v);
            tile[ty + 8 * j][tx] = v;
        }
        __syncthreads();
#pragma unroll
        for (int j = 0; j < 4; ++j)
            ot[(size_t)(n0 + ty + 8 * j) * C_ + c0 + tx] = __float2half_rn(tile[tx][ty + 8 * j]);
    } else {
        int s = (z - 48) >> 4, b = (z - 48) & 15;
        const float* ib = sel3cf(s, in1, in2, in3) + (size_t)b * C_ * N_;
        __half* ot = sel3h(s, i1T, i2T, i3T) + (size_t)b * N_ * C_;
#pragma unroll
        for (int j = 0; j < 4; ++j)
            tile[ty + 8 * j][tx] = ib[(size_t)(c0 + ty + 8 * j) * N_ + n0 + tx];
        __syncthreads();
#pragma unroll
        for (int j = 0; j < 4; ++j)
            ot[(size_t)(n0 + ty + 8 * j) * C_ + c0 + tx] = __float2half_rn(tile[tx][ty + 8 * j]);
    }
}

// ---------------------------------------------------------------------------
// Host orchestration
// ---------------------------------------------------------------------------
extern "C" void kernel_launch(void* const* d_in, const int* in_sizes, int n_in,
                              void* d_out, int out_size) {
    const float* in1      = (const float*)d_in[0];
    const float* in2      = (const float*)d_in[1];
    const float* in3      = (const float*)d_in[2];
    const float* w_fusion = (const float*)d_in[3];
    const float* b_fusion = (const float*)d_in[4];
    const float* w_out    = (const float*)d_in[5];
    const float* b_out    = (const float*)d_in[6];
    const float* w_reset  = (const float*)d_in[7];
    const float* b_reset  = (const float*)d_in[8];
    const float* w_update = (const float*)d_in[9];
    const float* b_update = (const float*)d_in[10];
    const float* w_cand   = (const float*)d_in[11];
    const float* b_cand   = (const float*)d_in[12];
    float* out = (float*)d_out;

    cudaFuncSetAttribute(k_scores_all,   cudaFuncAttributeMaxDynamicSharedMemorySize, SMEM_DYN);
    cudaFuncSetAttribute(k_attmmT_all,   cudaFuncAttributeMaxDynamicSharedMemorySize, SMEM_DYN);
    cudaFuncSetAttribute(k_conv3T_all,   cudaFuncAttributeMaxDynamicSharedMemorySize, SMEM_DYN);
    cudaFuncSetAttribute(k_gemmRU_all,   cudaFuncAttributeMaxDynamicSharedMemorySize, SMEM_DYN);
    cudaFuncSetAttribute(k_gemmCAND_all, cudaFuncAttributeMaxDynamicSharedMemorySize, SMEM_DYN);
    cudaFuncSetAttribute(k_conv3_all,    cudaFuncAttributeMaxDynamicSharedMemorySize, SMEM_DYN);

    float *S, *ex, *q, *q1, *u, *c;
    __half *P16, *OT, *aT, *rhT, *in1T, *in2T, *in3T;
    __half *wf16, *wo16, *wru16, *wc16;
    __half *m16a[3], *m16b[3], *mTa[3], *mTb[3];
    cudaGetSymbolAddress((void**)&S,    g_S);
    cudaGetSymbolAddress((void**)&ex,   g_ex);
    cudaGetSymbolAddress((void**)&q,    g_q);
    cudaGetSymbolAddress((void**)&q1,   g_q1);
    cudaGetSymbolAddress((void**)&u,    g_u);
    cudaGetSymbolAddress((void**)&c,    g_c);
    cudaGetSymbolAddress((void**)&P16,  g_P16);
    cudaGetSymbolAddress((void**)&OT,   g_OT);
    cudaGetSymbolAddress((void**)&aT,   g_aT);
    cudaGetSymbolAddress((void**)&rhT,  g_rhT);
    cudaGetSymbolAddress((void**)&in1T, g_in1T16);
    cudaGetSymbolAddress((void**)&in2T, g_in2T16);
    cudaGetSymbolAddress((void**)&in3T, g_in3T16);
    cudaGetSymbolAddress((void**)&wf16, g_wf16);
    cudaGetSymbolAddress((void**)&wo16, g_wo16);
    cudaGetSymbolAddress((void**)&wru16, g_wru16);
    cudaGetSymbolAddress((void**)&wc16, g_wc16);
    cudaGetSymbolAddress((void**)&m16a[0], g_ex16a);
    cudaGetSymbolAddress((void**)&m16a[1], g_q16a);
    cudaGetSymbolAddress((void**)&m16a[2], g_q116a);
    cudaGetSymbolAddress((void**)&m16b[0], g_ex16b);
    cudaGetSymbolAddress((void**)&m16b[1], g_q16b);
    cudaGetSymbolAddress((void**)&m16b[2], g_q116b);
    cudaGetSymbolAddress((void**)&mTa[0], g_exT16a);
    cudaGetSymbolAddress((void**)&mTa[1], g_qT16a);
    cudaGetSymbolAddress((void**)&mTa[2], g_q1T16a);
    cudaGetSymbolAddress((void**)&mTb[0], g_exT16b);
    cudaGetSymbolAddress((void**)&mTb[1], g_qT16b);
    cudaGetSymbolAddress((void**)&mTb[2], g_q1T16b);

    const int WTG = (int)((WTSZ + 255) / 256);
    const int GG  = (int)((3 * (size_t)C_ * 2 * C_ + 255) / 256);

    // prep (3 launches)
    k_prep_w<<<dim3(WTG, 2), 256>>>(w_fusion, w_out, wf16, wo16);
    k_prep_g<<<GG, 256>>>(w_reset, w_update, w_cand, wru16, wc16);
    k_premirror<<<dim3(32, 16, 96), dim3(32, 8)>>>(
        in1, in2, in3, ex, q, q1,
        m16a[0], m16a[1], m16a[2], mTa[0], mTa[1], mTa[2],
        in1T, in2T, in3T);

    __half** cur16 = m16a;  __half** curT = mTa;
    __half** nw16  = m16b;  __half** nwT  = mTb;

    for (int round = 0; round < 5; ++round) {
        k_scores_all<<<dim3(8, 8, 96), 128, SMEM_DYN>>>(curT[0], curT[1], curT[2], S);
        k_softmax_all<<<6 * B_ * N_, 256>>>(S, P16);
        k_attmmT_all<<<dim3(4, 8, 96), 128, SMEM_DYN>>>(P16, cur16[0], cur16[1], cur16[2], OT);
        k_conv3T_all<<<dim3(4, 8, 48), 128, SMEM_DYN>>>(wf16, OT, b_fusion, aT);
        k_gemmRU_all<<<dim3(8, 8, 48), 128, SMEM_DYN>>>(
            wru16, aT, curT[0], curT[1], curT[2], ex, q, q1,
            b_reset, b_update, rhT, u);
        k_gemmCAND_all<<<dim3(8, 4, 48), 128, SMEM_DYN>>>(wc16, aT, rhT, b_cand, c);
        k_gruout_all<<<dim3(32, 16, 48), dim3(32, 8)>>>(
            ex, q, q1, u, c,
            nw16[0], nw16[1], nw16[2], nwT[0], nwT[1], nwT[2]);

        __half** t16 = cur16; cur16 = nw16; nw16 = t16;
        __half** tT  = curT;  curT  = nwT;  nwT  = tT;
    }

    k_conv3_all<<<dim3(8, 4, 48), 128, SMEM_DYN>>>(
        wo16, curT[0], curT[1], curT[2], in1T, in2T, in3T, b_out, out);
}